// round 7
// baseline (speedup 1.0000x reference)
#include <cuda_runtime.h>
#include <cstdint>

// Problem constants (B=32, H=W=56, C=384, heads=12, ws=7, shift=3)
#define HEADS   12
#define WS      7
#define NTOK    49
#define NWIN    2048
#define M_TOTAL (NWIN * NTOK)   // 100352
#define N_QKV   1152
#define N_PROJ  384
#define KDIM    384

// GEMM tiling: CTA 128x128, 256 threads (8 warps, warp tile 64x32),
// BK=16, 4-stage cp.async ring, LDS.64 paired fragments, and
// cross-barrier register fragment prefetch (zero post-barrier LDS bubble).
// K values inside every 8-float group are stored permuted [0,4,1,5,2,6,3,7].
#define BM 128
#define BN 128
#define BK 16
#define KSTEPS (KDIM / BK)        // 24
#define APAD 24                   // row stride (floats): LDS.64 conflict-free
#define STAGE_FLOATS (BM * APAD)  // 3072
#define AB_STAGE (2 * STAGE_FLOATS)
#define NSTG 4
#define SMEM_BYTES (NSTG * AB_STAGE * 4)   // 98304

// Scratch (__device__ globals: sanctioned allocation-free path)
__device__ float g_qkv[(size_t)M_TOTAL * N_QKV];
__device__ float g_attn[(size_t)M_TOTAL * N_PROJ];
__device__ float g_xr  [(size_t)M_TOTAL * KDIM];
__device__ float g_wtq [(size_t)N_QKV * KDIM];
__device__ float g_wtp [(size_t)N_PROJ * KDIM];

// ---------------------------------------------------------------------------
// roll+window gather map (shift is involution-symmetric): m = win*49 + t
__device__ __forceinline__ int win_src_index(int m) {
    int win = m / NTOK, t = m - win * NTOK;
    int b  = win >> 6, wi = win & 63;
    int wh = wi >> 3,  ww = wi & 7;
    int r  = t / WS,   c  = t - r * WS;
    int row = wh * WS + r + 3; if (row >= 56) row -= 56;
    int col = ww * WS + c + 3; if (col >= 56) col -= 56;
    return b * 3136 + row * 56 + col;
}

__device__ __forceinline__ uint32_t smem_u32(const void* p) {
    uint32_t a;
    asm("{ .reg .u64 t; cvta.to.shared.u64 t, %1; cvt.u32.u64 %0, t; }" : "=r"(a) : "l"(p));
    return a;
}
__device__ __forceinline__ float round_tf32(float v) {
    uint32_t r;
    asm("cvt.rna.tf32.f32 %0, %1;" : "=r"(r) : "f"(v));
    return __uint_as_float(r);
}

#define CP16(dst, src) \
    asm volatile("cp.async.cg.shared.global [%0], [%1], 16;" :: "r"(dst), "l"(src) : "memory")
#define CP_COMMIT() asm volatile("cp.async.commit_group;" ::: "memory")
#define CP_WAIT1()  asm volatile("cp.async.wait_group 1;" ::: "memory")
#define CP_WAIT0()  asm volatile("cp.async.wait_group 0;" ::: "memory")

#define MMA_TF32(c, a, b) \
    asm volatile("mma.sync.aligned.m16n8k8.row.col.f32.tf32.tf32.f32 " \
        "{%0,%1,%2,%3}, {%4,%5,%6,%7}, {%8,%9}, {%0,%1,%2,%3};" \
        : "+f"((c)[0]), "+f"((c)[1]), "+f"((c)[2]), "+f"((c)[3]) \
        : "r"((a)[0]), "r"((a)[1]), "r"((a)[2]), "r"((a)[3]), "r"((b)[0]), "r"((b)[1]))

struct Frag { uint32_t a[4][4]; uint32_t b[4][2]; };

// ---------------------------------------------------------------------------
// tf32 mma.sync GEMM. GATHER fuses roll/window into A rows, SCATTER into C rows.
template <int N_TOTAL, bool GATHER, bool SCATTER>
__global__ void __launch_bounds__(256, 2)
gemm_mma(const float* __restrict__ A, const float* __restrict__ WT,
         const float* __restrict__ bias, float* __restrict__ C)
{
    extern __shared__ float sm[];
    const uint32_t smb = smem_u32(sm);

    const int tid  = threadIdx.x;
    const int wid  = tid >> 5, lane = tid & 31;
    const int g    = lane >> 2, t = lane & 3;
    const int wm   = wid & 1, wn = wid >> 1;       // warp grid 2(M) x 4(N)
    const int m0   = blockIdx.y * BM, n0 = blockIdx.x * BN;

    // loads: 2 threads per row, 8 floats (32B = 2x CP16) each
    const int lrow = tid >> 1, lseg = (tid & 1) * 8;
    const float* arow = A + (size_t)(GATHER ? win_src_index(m0 + lrow) : (m0 + lrow)) * KDIM + lseg;
    const float* brow = WT + (size_t)(n0 + lrow) * KDIM + lseg;
    const uint32_t a_dst = smb + ((uint32_t)lrow * APAD + lseg) * 4;
    const uint32_t b_dst = a_dst + STAGE_FLOATS * 4;

    auto load_stage = [&](int s, int kt) {
        const uint32_t so = (uint32_t)s * AB_STAGE * 4;
        const float* ap = arow + kt * BK;
        const float* bp = brow + kt * BK;
        CP16(a_dst + so,      ap);
        CP16(a_dst + so + 16, ap + 4);
        CP16(b_dst + so,      bp);
        CP16(b_dst + so + 16, bp + 4);
    };

    auto load_frags = [&](Frag& f, const uint2* AsU2, const uint2* BsU2, int ko4) {
#pragma unroll
        for (int i = 0; i < 4; i++) {
            const int r2 = (wm * 64 + i * 16 + g) * (APAD / 2) + ko4 + t;
            uint2 p0 = AsU2[r2];
            uint2 p1 = AsU2[r2 + 8 * (APAD / 2)];
            f.a[i][0] = p0.x; f.a[i][1] = p1.x; f.a[i][2] = p0.y; f.a[i][3] = p1.y;
        }
#pragma unroll
        for (int j = 0; j < 4; j++) {
            const int n2 = (wn * 32 + j * 8 + g) * (APAD / 2) + ko4 + t;
            uint2 q = BsU2[n2];
            f.b[j][0] = q.x; f.b[j][1] = q.y;
        }
    };

    float c[4][4][4];
#pragma unroll
    for (int i = 0; i < 4; i++)
#pragma unroll
        for (int j = 0; j < 4; j++)
#pragma unroll
            for (int q = 0; q < 4; q++) c[i][j][q] = 0.f;

    auto mma_frag = [&](const Frag& f) {
#pragma unroll
        for (int i = 0; i < 4; i++)
#pragma unroll
            for (int j = 0; j < 4; j++) MMA_TF32(c[i][j], f.a[i], f.b[j]);
    };

    // prologue: fill NSTG-1 stages; make slots 0 and 1 visible; preload frags(0,ks0)
#pragma unroll
    for (int s = 0; s < NSTG - 1; s++) { load_stage(s, s); CP_COMMIT(); }
    CP_WAIT1();
    __syncthreads();

    Frag f0, f1;
    load_frags(f0, (const uint2*)sm, (const uint2*)sm + STAGE_FLOATS / 2, 0);

    for (int kt = 0; kt < KSTEPS; kt++) {
        const uint2* AsU2 = (const uint2*)(sm + (kt & 3) * AB_STAGE);
        const uint2* BsU2 = AsU2 + STAGE_FLOATS / 2;

        // gmem prefetch into the slot consumed at kt-1 (barrier-protected)
        if (kt + NSTG - 1 < KSTEPS) { load_stage((kt + NSTG - 1) & 3, kt + NSTG - 1); CP_COMMIT(); }

        load_frags(f1, AsU2, BsU2, 4);      // (kt, ks1)
        mma_frag(f0);                        // (kt, ks0) — regs ready at barrier exit
        if (kt + 1 < KSTEPS) {
            // (kt+1, ks0): slot kt+1 visible since the previous barrier (wait_group 1)
            const uint2* An = (const uint2*)(sm + ((kt + 1) & 3) * AB_STAGE);
            load_frags(f0, An, An + STAGE_FLOATS / 2, 0);
        }
        mma_frag(f1);                        // (kt, ks1) — hides f0 LDS latency

        if (kt + 1 < KSTEPS) {
            if (kt < KSTEPS - 3) CP_WAIT1(); else CP_WAIT0();
            __syncthreads();
        }
    }

    // reg-direct epilogue: each 4-lane group stores 32B contiguous (1 sector)
    const int ncolb = n0 + wn * 32;
    float2 bj[4];
#pragma unroll
    for (int j = 0; j < 4; j++)
        bj[j] = *reinterpret_cast<const float2*>(&bias[ncolb + j * 8 + 2 * t]);

#pragma unroll
    for (int i = 0; i < 4; i++) {
        const int mrow = m0 + wm * 64 + i * 16 + g;
        const size_t r0 = SCATTER ? (size_t)win_src_index(mrow)     : (size_t)mrow;
        const size_t r1 = SCATTER ? (size_t)win_src_index(mrow + 8) : (size_t)(mrow + 8);
        float* p0 = C + r0 * N_TOTAL + ncolb + 2 * t;
        float* p1 = C + r1 * N_TOTAL + ncolb + 2 * t;
#pragma unroll
        for (int j = 0; j < 4; j++) {
            *reinterpret_cast<float2*>(p0 + j * 8) =
                make_float2(c[i][j][0] + bj[j].x, c[i][j][1] + bj[j].y);
            *reinterpret_cast<float2*>(p1 + j * 8) =
                make_float2(c[i][j][2] + bj[j].x, c[i][j][3] + bj[j].y);
        }
    }
}

// ---------------------------------------------------------------------------
// Preprocessing: transpose W[K][N] -> WT[N][Kperm], rounded to tf32 (rna)
__global__ void transpose_round(const float* __restrict__ W, float* __restrict__ WT,
                                int K, int N)
{
    __shared__ float tbuf[32][33];
    const int n0 = blockIdx.x * 32, k0 = blockIdx.y * 32;
    const int tx = threadIdx.x, ty = threadIdx.y;   // 32 x 8
#pragma unroll
    for (int i = 0; i < 4; i++)
        tbuf[ty + 8 * i][tx] = W[(size_t)(k0 + ty + 8 * i) * N + n0 + tx];
    __syncthreads();
    // permute k within each 8-group: k -> (k&~7) | 2*(k&3) | ((k>>2)&1)
    const int kpos = (tx & ~7) | ((tx & 3) * 2) | ((tx >> 2) & 1);
#pragma unroll
    for (int i = 0; i < 4; i++)
        WT[(size_t)(n0 + ty + 8 * i) * K + k0 + kpos] = round_tf32(tbuf[tx][ty + 8 * i]);
}

// x -> tf32-rounded, k-pair-permuted copy (per 8-float group)
__global__ void round_x_perm(const float4* __restrict__ in, float4* __restrict__ out, int n8)
{
    int i = blockIdx.x * blockDim.x + threadIdx.x;
    if (i < n8) {
        float4 v0 = in[2 * i], v1 = in[2 * i + 1];
        v0.x = round_tf32(v0.x); v0.y = round_tf32(v0.y);
        v0.z = round_tf32(v0.z); v0.w = round_tf32(v0.w);
        v1.x = round_tf32(v1.x); v1.y = round_tf32(v1.y);
        v1.z = round_tf32(v1.z); v1.w = round_tf32(v1.w);
        out[2 * i]     = make_float4(v0.x, v1.x, v0.y, v1.y);   // k0,k4,k1,k5
        out[2 * i + 1] = make_float4(v0.z, v1.z, v0.w, v1.w);   // k2,k6,k3,k7
    }
}

// ---------------------------------------------------------------------------
// Per-(window, head) attention: 49x32 Q,K,V -> softmax(QK^T*scale + bias) V
__global__ void __launch_bounds__(64)
attn_kernel(const float* __restrict__ bias_table)
{
    const int blk  = blockIdx.x;
    const int head = blk % HEADS;
    const int win  = blk / HEADS;

    __shared__ float Qs[NTOK * 36];
    __shared__ float Ks[NTOK * 32];
    __shared__ float Vs[NTOK * 32];
    __shared__ float Os[NTOK * 36];
    __shared__ float Ss[NTOK * 50];
    __shared__ float Bb[169];

    const int tid = threadIdx.x;
    const float* base = g_qkv + (size_t)win * NTOK * N_QKV + head * 32;

    for (int idx = tid; idx < 169; idx += 64)
        Bb[idx] = __ldg(&bias_table[idx * HEADS + head]);
    for (int idx = tid; idx < NTOK * 8; idx += 64) {
        int tt = idx >> 3, w = idx & 7;
        const float4* p = reinterpret_cast<const float4*>(base + (size_t)tt * N_QKV) + w;
        reinterpret_cast<float4*>(Qs)[tt * 9 + w] = p[0];
        reinterpret_cast<float4*>(Ks)[tt * 8 + w] = p[96];    // +384 floats
        reinterpret_cast<float4*>(Vs)[tt * 8 + w] = p[192];   // +768 floats
    }
    __syncthreads();

    if (tid < NTOK) {
        const int i  = tid;
        const int ri = i / WS, ci = i - ri * WS;
        const float scale = 0.17677669529663687f;

        float4 q[8];
        const float4* Q4 = reinterpret_cast<const float4*>(Qs);
        const float4* K4 = reinterpret_cast<const float4*>(Ks);
        const float4* V4 = reinterpret_cast<const float4*>(Vs);
#pragma unroll
        for (int w = 0; w < 8; w++) q[w] = Q4[i * 9 + w];

        float mx = -1e30f;
        for (int j = 0; j < NTOK; j++) {
            float acc = 0.f;
#pragma unroll
            for (int w = 0; w < 8; w++) {
                float4 k = K4[j * 8 + w];
                acc += q[w].x * k.x + q[w].y * k.y + q[w].z * k.z + q[w].w * k.w;
            }
            int rj = j / WS, cj = j - rj * WS;
            int rel = (ri - rj + 6) * 13 + (ci - cj + 6);
            acc = acc * scale + Bb[rel];
            Ss[i * 50 + j] = acc;
            mx = fmaxf(mx, acc);
        }
        float sum = 0.f;
        for (int j = 0; j < NTOK; j++) {
            float p = __expf(Ss[i * 50 + j] - mx);
            Ss[i * 50 + j] = p;
            sum += p;
        }
        const float inv = 1.0f / sum;

        float4 o[8];
#pragma unroll
        for (int w = 0; w < 8; w++) o[w] = make_float4(0.f, 0.f, 0.f, 0.f);
        for (int j = 0; j < NTOK; j++) {
            float p = Ss[i * 50 + j] * inv;
#pragma unroll
            for (int w = 0; w < 8; w++) {
                float4 v = V4[j * 8 + w];
                o[w].x += p * v.x; o[w].y += p * v.y;
                o[w].z += p * v.z; o[w].w += p * v.w;
            }
        }
        // round + k-pair permute per 8-dim group for the proj GEMM
        float4* O4 = reinterpret_cast<float4*>(Os);
#pragma unroll
        for (int g2 = 0; g2 < 4; g2++) {
            float4 e = o[2 * g2], f = o[2 * g2 + 1];
            e.x = round_tf32(e.x); e.y = round_tf32(e.y);
            e.z = round_tf32(e.z); e.w = round_tf32(e.w);
            f.x = round_tf32(f.x); f.y = round_tf32(f.y);
            f.z = round_tf32(f.z); f.w = round_tf32(f.w);
            O4[i * 9 + 2 * g2]     = make_float4(e.x, f.x, e.y, f.y);
            O4[i * 9 + 2 * g2 + 1] = make_float4(e.z, f.z, e.w, f.w);
        }
    }
    __syncthreads();

    float* outbase = g_attn + (size_t)win * NTOK * N_PROJ + head * 32;
    for (int idx = tid; idx < NTOK * 8; idx += 64) {
        int tt = idx >> 3, w = idx & 7;
        reinterpret_cast<float4*>(outbase + (size_t)tt * N_PROJ)[w] =
            reinterpret_cast<const float4*>(Os)[tt * 9 + w];
    }
}

// ---------------------------------------------------------------------------
extern "C" void kernel_launch(void* const* d_in, const int* in_sizes, int n_in,
                              void* d_out, int out_size)
{
    const float* x          = (const float*)d_in[0];
    const float* qkv_w      = (const float*)d_in[1];
    const float* qkv_b      = (const float*)d_in[2];
    const float* proj_w     = (const float*)d_in[3];
    const float* proj_b     = (const float*)d_in[4];
    const float* bias_table = (const float*)d_in[5];
    float* out = (float*)d_out;

    float *qkv_p, *attn_p, *xr_p, *wtq_p, *wtp_p;
    cudaGetSymbolAddress((void**)&qkv_p,  g_qkv);
    cudaGetSymbolAddress((void**)&attn_p, g_attn);
    cudaGetSymbolAddress((void**)&xr_p,   g_xr);
    cudaGetSymbolAddress((void**)&wtq_p,  g_wtq);
    cudaGetSymbolAddress((void**)&wtp_p,  g_wtp);

    cudaFuncSetAttribute(gemm_mma<N_QKV, true, false>,
                         cudaFuncAttributeMaxDynamicSharedMemorySize, SMEM_BYTES);
    cudaFuncSetAttribute(gemm_mma<N_PROJ, false, true>,
                         cudaFuncAttributeMaxDynamicSharedMemorySize, SMEM_BYTES);

    // 0) preprocessing (tf32 rna rounding; k-pair permutation; weights -> K-major)
    {
        int n8 = M_TOTAL * KDIM / 8;
        round_x_perm<<<(n8 + 255) / 256, 256>>>((const float4*)x, (float4*)xr_p, n8);
        transpose_round<<<dim3(N_QKV / 32, KDIM / 32), dim3(32, 8)>>>(qkv_w, wtq_p, KDIM, N_QKV);
        transpose_round<<<dim3(N_PROJ / 32, KDIM / 32), dim3(32, 8)>>>(proj_w, wtp_p, KDIM, N_PROJ);
    }
    // 1) QKV GEMM (tf32 mma.sync, fused window/roll gather)
    gemm_mma<N_QKV, true, false><<<dim3(N_QKV / BN, M_TOTAL / BM), 256, SMEM_BYTES>>>(
        xr_p, wtq_p, qkv_b, qkv_p);
    // 2) window attention
    attn_kernel<<<NWIN * HEADS, 64>>>(bias_table);
    // 3) proj GEMM (tf32 mma.sync, fused inverse roll/window scatter)
    gemm_mma<N_PROJ, false, true><<<dim3(N_PROJ / BN, M_TOTAL / BM), 256, SMEM_BYTES>>>(
        attn_p, wtp_p, proj_b, out);
}

// round 8
// speedup vs baseline: 1.0442x; 1.0442x over previous
#include <cuda_runtime.h>
#include <cstdint>

// Problem constants (B=32, H=W=56, C=384, heads=12, ws=7, shift=3)
#define HEADS   12
#define WS      7
#define NTOK    49
#define NWIN    2048
#define M_TOTAL (NWIN * NTOK)   // 100352
#define N_QKV   1152
#define N_PROJ  384
#define KDIM    384

// GEMM tiling (R6 known-good): CTA 128x128, 256 threads, BK=16, 4-stage ring,
// LDS.64 paired fragments via k-pair permutation [0,4,1,5,2,6,3,7].
#define BM 128
#define BN 128
#define BK 16
#define KSTEPS (KDIM / BK)        // 24
#define APAD 24
#define STAGE_FLOATS (BM * APAD)  // 3072
#define AB_STAGE (2 * STAGE_FLOATS)
#define NSTG 4
#define SMEM_BYTES (NSTG * AB_STAGE * 4)   // 98304

// Scratch (__device__ globals: sanctioned allocation-free path)
__device__ float g_qkv[(size_t)M_TOTAL * N_QKV];
__device__ float g_attn[(size_t)M_TOTAL * N_PROJ];
__device__ float g_xr  [(size_t)M_TOTAL * KDIM];
__device__ float g_wtq [(size_t)N_QKV * KDIM];
__device__ float g_wtp [(size_t)N_PROJ * KDIM];

// ---------------------------------------------------------------------------
__device__ __forceinline__ int win_src_index(int m) {
    int win = m / NTOK, t = m - win * NTOK;
    int b  = win >> 6, wi = win & 63;
    int wh = wi >> 3,  ww = wi & 7;
    int r  = t / WS,   c  = t - r * WS;
    int row = wh * WS + r + 3; if (row >= 56) row -= 56;
    int col = ww * WS + c + 3; if (col >= 56) col -= 56;
    return b * 3136 + row * 56 + col;
}

__device__ __forceinline__ uint32_t smem_u32(const void* p) {
    uint32_t a;
    asm("{ .reg .u64 t; cvta.to.shared.u64 t, %1; cvt.u32.u64 %0, t; }" : "=r"(a) : "l"(p));
    return a;
}
__device__ __forceinline__ float round_tf32(float v) {
    uint32_t r;
    asm("cvt.rna.tf32.f32 %0, %1;" : "=r"(r) : "f"(v));
    return __uint_as_float(r);
}

#define CP16(dst, src) \
    asm volatile("cp.async.cg.shared.global [%0], [%1], 16;" :: "r"(dst), "l"(src) : "memory")
#define CP_COMMIT() asm volatile("cp.async.commit_group;" ::: "memory")
#define CP_WAIT2()  asm volatile("cp.async.wait_group 2;" ::: "memory")
#define CP_WAIT1()  asm volatile("cp.async.wait_group 1;" ::: "memory")
#define CP_WAIT0()  asm volatile("cp.async.wait_group 0;" ::: "memory")

#define MMA_TF32(c, a, b) \
    asm volatile("mma.sync.aligned.m16n8k8.row.col.f32.tf32.tf32.f32 " \
        "{%0,%1,%2,%3}, {%4,%5,%6,%7}, {%8,%9}, {%0,%1,%2,%3};" \
        : "+f"((c)[0]), "+f"((c)[1]), "+f"((c)[2]), "+f"((c)[3]) \
        : "r"((a)[0]), "r"((a)[1]), "r"((a)[2]), "r"((a)[3]), "r"((b)[0]), "r"((b)[1]))

// ---------------------------------------------------------------------------
// tf32 mma.sync GEMM (R6 loop, verbatim). GATHER/SCATTER fuse the roll/window map.
template <int N_TOTAL, bool GATHER, bool SCATTER>
__global__ void __launch_bounds__(256, 2)
gemm_mma(const float* __restrict__ A, const float* __restrict__ WT,
         const float* __restrict__ bias, float* __restrict__ C)
{
    extern __shared__ float sm[];
    const uint32_t smb = smem_u32(sm);

    const int tid  = threadIdx.x;
    const int wid  = tid >> 5, lane = tid & 31;
    const int g    = lane >> 2, t = lane & 3;
    const int wm   = wid & 1, wn = wid >> 1;
    const int m0   = blockIdx.y * BM, n0 = blockIdx.x * BN;

    const int lrow = tid >> 1, lseg = (tid & 1) * 8;
    const float* arow = A + (size_t)(GATHER ? win_src_index(m0 + lrow) : (m0 + lrow)) * KDIM + lseg;
    const float* brow = WT + (size_t)(n0 + lrow) * KDIM + lseg;
    const uint32_t a_dst = smb + ((uint32_t)lrow * APAD + lseg) * 4;
    const uint32_t b_dst = a_dst + STAGE_FLOATS * 4;

    auto load_stage = [&](int s, int kt) {
        const uint32_t so = (uint32_t)s * AB_STAGE * 4;
        const float* ap = arow + kt * BK;
        const float* bp = brow + kt * BK;
        CP16(a_dst + so,      ap);
        CP16(a_dst + so + 16, ap + 4);
        CP16(b_dst + so,      bp);
        CP16(b_dst + so + 16, bp + 4);
    };

    float c[4][4][4];
#pragma unroll
    for (int i = 0; i < 4; i++)
#pragma unroll
        for (int j = 0; j < 4; j++)
#pragma unroll
            for (int q = 0; q < 4; q++) c[i][j][q] = 0.f;

#pragma unroll
    for (int s = 0; s < NSTG - 1; s++) { load_stage(s, s); CP_COMMIT(); }

#pragma unroll 4
    for (int kt = 0; kt < KSTEPS; kt++) {
        const int rem = KSTEPS - 1 - kt;
        if (rem >= 2)      CP_WAIT2();
        else if (rem == 1) CP_WAIT1();
        else               CP_WAIT0();
        __syncthreads();

        if (kt + NSTG - 1 < KSTEPS) { load_stage((kt + NSTG - 1) & 3, kt + NSTG - 1); CP_COMMIT(); }

        const uint2* AsU2 = (const uint2*)(sm + (kt & 3) * AB_STAGE);
        const uint2* BsU2 = AsU2 + STAGE_FLOATS / 2;

#pragma unroll
        for (int ks = 0; ks < 2; ks++) {
            const int ko4 = ks * 4;
            uint32_t a[4][4];
#pragma unroll
            for (int i = 0; i < 4; i++) {
                const int r2 = (wm * 64 + i * 16 + g) * (APAD / 2) + ko4 + t;
                uint2 p0 = AsU2[r2];
                uint2 p1 = AsU2[r2 + 8 * (APAD / 2)];
                a[i][0] = p0.x; a[i][1] = p1.x; a[i][2] = p0.y; a[i][3] = p1.y;
            }
            uint32_t b[4][2];
#pragma unroll
            for (int j = 0; j < 4; j++) {
                const int n2 = (wn * 32 + j * 8 + g) * (APAD / 2) + ko4 + t;
                uint2 q = BsU2[n2];
                b[j][0] = q.x; b[j][1] = q.y;
            }
#pragma unroll
            for (int i = 0; i < 4; i++)
#pragma unroll
                for (int j = 0; j < 4; j++) MMA_TF32(c[i][j], a[i], b[j]);
        }
    }

    const int ncolb = n0 + wn * 32;
    float2 bj[4];
#pragma unroll
    for (int j = 0; j < 4; j++)
        bj[j] = *reinterpret_cast<const float2*>(&bias[ncolb + j * 8 + 2 * t]);

#pragma unroll
    for (int i = 0; i < 4; i++) {
        const int mrow = m0 + wm * 64 + i * 16 + g;
        const size_t r0 = SCATTER ? (size_t)win_src_index(mrow)     : (size_t)mrow;
        const size_t r1 = SCATTER ? (size_t)win_src_index(mrow + 8) : (size_t)(mrow + 8);
        float* p0 = C + r0 * N_TOTAL + ncolb + 2 * t;
        float* p1 = C + r1 * N_TOTAL + ncolb + 2 * t;
#pragma unroll
        for (int j = 0; j < 4; j++) {
            *reinterpret_cast<float2*>(p0 + j * 8) =
                make_float2(c[i][j][0] + bj[j].x, c[i][j][1] + bj[j].y);
            *reinterpret_cast<float2*>(p1 + j * 8) =
                make_float2(c[i][j][2] + bj[j].x, c[i][j][3] + bj[j].y);
        }
    }
}

// ---------------------------------------------------------------------------
// Preprocessing
__global__ void transpose_round(const float* __restrict__ W, float* __restrict__ WT,
                                int K, int N)
{
    __shared__ float tbuf[32][33];
    const int n0 = blockIdx.x * 32, k0 = blockIdx.y * 32;
    const int tx = threadIdx.x, ty = threadIdx.y;
#pragma unroll
    for (int i = 0; i < 4; i++)
        tbuf[ty + 8 * i][tx] = W[(size_t)(k0 + ty + 8 * i) * N + n0 + tx];
    __syncthreads();
    const int kpos = (tx & ~7) | ((tx & 3) * 2) | ((tx >> 2) & 1);
#pragma unroll
    for (int i = 0; i < 4; i++)
        WT[(size_t)(n0 + ty + 8 * i) * K + k0 + kpos] = round_tf32(tbuf[tx][ty + 8 * i]);
}

__global__ void round_x_perm(const float4* __restrict__ in, float4* __restrict__ out, int n8)
{
    int i = blockIdx.x * blockDim.x + threadIdx.x;
    if (i < n8) {
        float4 v0 = in[2 * i], v1 = in[2 * i + 1];
        v0.x = round_tf32(v0.x); v0.y = round_tf32(v0.y);
        v0.z = round_tf32(v0.z); v0.w = round_tf32(v0.w);
        v1.x = round_tf32(v1.x); v1.y = round_tf32(v1.y);
        v1.z = round_tf32(v1.z); v1.w = round_tf32(v1.w);
        out[2 * i]     = make_float4(v0.x, v1.x, v0.y, v1.y);
        out[2 * i + 1] = make_float4(v0.z, v1.z, v0.w, v1.w);
    }
}

// ---------------------------------------------------------------------------
// Tensor-core window attention: one warp per (window, head).
// QK^T: M=64(pad 49) x N=56(pad 49) x K=32 tf32 mma; masked softmax in regs
// (4-lane shfl reductions); P -> smem; PV: M=64 x N=32 x K=56(pad 49) mma.
// Output written tf32-rounded + k-pair-permuted for the proj GEMM.
__global__ void __launch_bounds__(32)
attn_mma_kernel(const float* __restrict__ bias_table)
{
    const int blk  = blockIdx.x;
    const int head = blk % HEADS;
    const int win  = blk / HEADS;
    const int lane = threadIdx.x;
    const int g = lane >> 2, t = lane & 3;

    __shared__ float SQ[64 * 60];   // Q (stride 36), later P (stride 60)
    __shared__ float Ks[56 * 36];
    __shared__ float Vs[56 * 40];
    __shared__ float Bb[224];       // bias with +-13 guard pad: index 13+rel

    // bias staging (guard-padded, zero outside)
    for (int i = lane; i < 224; i += 32) Bb[i] = 0.f;
    __syncwarp();
    for (int i = lane; i < 169; i += 32) Bb[13 + i] = __ldg(&bias_table[i * HEADS + head]);

    // zero pad rows (Q rows 49..63, K rows 49..55, V rows 49..55)
    const float4 z4 = make_float4(0.f, 0.f, 0.f, 0.f);
    for (int i = lane; i < 15 * 9; i += 32)
        *reinterpret_cast<float4*>(&SQ[(49 + i / 9) * 36 + (i % 9) * 4]) = z4;
    for (int i = lane; i < 7 * 9; i += 32)
        *reinterpret_cast<float4*>(&Ks[(49 + i / 9) * 36 + (i % 9) * 4]) = z4;
    for (int i = lane; i < 7 * 10; i += 32)
        *reinterpret_cast<float4*>(&Vs[(49 + i / 10) * 40 + (i % 10) * 4]) = z4;

    // stage Q,K,V (tf32-rounded)
    const float* qbase = g_qkv + (size_t)(win * NTOK) * N_QKV + head * 32;
    for (int idx = lane; idx < NTOK * 8; idx += 32) {
        int row = idx >> 3, w = idx & 7;
        const float4* p = reinterpret_cast<const float4*>(qbase + (size_t)row * N_QKV) + w;
        float4 q = p[0], k = p[96], v = p[192];
        q.x = round_tf32(q.x); q.y = round_tf32(q.y); q.z = round_tf32(q.z); q.w = round_tf32(q.w);
        k.x = round_tf32(k.x); k.y = round_tf32(k.y); k.z = round_tf32(k.z); k.w = round_tf32(k.w);
        v.x = round_tf32(v.x); v.y = round_tf32(v.y); v.z = round_tf32(v.z); v.w = round_tf32(v.w);
        *reinterpret_cast<float4*>(&SQ[row * 36 + w * 4]) = q;
        *reinterpret_cast<float4*>(&Ks[row * 36 + w * 4]) = k;
        *reinterpret_cast<float4*>(&Vs[row * 40 + w * 4]) = v;
    }
    __syncwarp();

    // ---- QK^T ----
    float c[4][7][4];
#pragma unroll
    for (int it = 0; it < 4; it++)
#pragma unroll
        for (int jt = 0; jt < 7; jt++)
#pragma unroll
            for (int q = 0; q < 4; q++) c[it][jt][q] = 0.f;

#pragma unroll
    for (int kt = 0; kt < 4; kt++) {
        const int ko = kt * 8;
        uint32_t a[4][4];
#pragma unroll
        for (int it = 0; it < 4; it++) {
            const uint32_t* ap = (const uint32_t*)&SQ[(it * 16 + g) * 36 + ko + t];
            a[it][0] = ap[0]; a[it][1] = ap[8 * 36]; a[it][2] = ap[4]; a[it][3] = ap[8 * 36 + 4];
        }
#pragma unroll
        for (int jt = 0; jt < 7; jt++) {
            const uint32_t* bp = (const uint32_t*)&Ks[(jt * 8 + g) * 36 + ko + t];
            uint32_t b[2] = { bp[0], bp[4] };
#pragma unroll
            for (int it = 0; it < 4; it++) MMA_TF32(c[it][jt], a[it], b);
        }
    }
    __syncwarp();

    // ---- masked bias add + softmax ----
    const float scale = 0.17677669529663687f;
    int  pi[8];  bool rok[8];
#pragma unroll
    for (int s = 0; s < 8; s++) {
        int tok = (s >> 1) * 16 + g + 8 * (s & 1);
        rok[s] = tok < NTOK;
        int ri = tok / 7, ci = tok - ri * 7;
        pi[s] = ri * 13 + ci + 97;            // +84 rel-offset +13 guard pad
    }
    int  pj[14]; bool cok[14];
#pragma unroll
    for (int u = 0; u < 14; u++) {
        int jc = (u >> 1) * 8 + 2 * t + (u & 1);
        cok[u] = jc < NTOK;
        int rj = jc / 7, cj = jc - rj * 7;
        pj[u] = rj * 13 + cj;
    }
#pragma unroll
    for (int it = 0; it < 4; it++)
#pragma unroll
        for (int jt = 0; jt < 7; jt++)
#pragma unroll
            for (int q = 0; q < 4; q++) {
                int s = it * 2 + (q >> 1), u = jt * 2 + (q & 1);
                float sc = c[it][jt][q] * scale + Bb[pi[s] - pj[u]];
                c[it][jt][q] = (rok[s] && cok[u]) ? sc : -1e9f;
            }

#pragma unroll
    for (int s = 0; s < 8; s++) {
        const int it = s >> 1, h = s & 1;
        float m = -1e9f;
#pragma unroll
        for (int jt = 0; jt < 7; jt++) {
            m = fmaxf(m, c[it][jt][h * 2]);
            m = fmaxf(m, c[it][jt][h * 2 + 1]);
        }
        m = fmaxf(m, __shfl_xor_sync(0xffffffffu, m, 1));
        m = fmaxf(m, __shfl_xor_sync(0xffffffffu, m, 2));
        float sum = 0.f;
#pragma unroll
        for (int jt = 0; jt < 7; jt++) {
            float p0 = __expf(c[it][jt][h * 2]     - m);
            float p1 = __expf(c[it][jt][h * 2 + 1] - m);
            c[it][jt][h * 2] = p0; c[it][jt][h * 2 + 1] = p1;
            sum += p0 + p1;
        }
        sum += __shfl_xor_sync(0xffffffffu, sum, 1);
        sum += __shfl_xor_sync(0xffffffffu, sum, 2);
        const float inv = 1.0f / sum;
#pragma unroll
        for (int jt = 0; jt < 7; jt++) {
            c[it][jt][h * 2]     = round_tf32(c[it][jt][h * 2]     * inv);
            c[it][jt][h * 2 + 1] = round_tf32(c[it][jt][h * 2 + 1] * inv);
        }
    }
    __syncwarp();

    // P -> smem (stride 60; overwrites Q region)
#pragma unroll
    for (int it = 0; it < 4; it++)
#pragma unroll
        for (int jt = 0; jt < 7; jt++) {
            float* p0 = &SQ[(it * 16 + g) * 60 + jt * 8 + 2 * t];
            *reinterpret_cast<float2*>(p0)            = make_float2(c[it][jt][0], c[it][jt][1]);
            *reinterpret_cast<float2*>(p0 + 8 * 60)   = make_float2(c[it][jt][2], c[it][jt][3]);
        }
    __syncwarp();

    // ---- PV ----
    float d2[4][4][4];
#pragma unroll
    for (int it = 0; it < 4; it++)
#pragma unroll
        for (int nt = 0; nt < 4; nt++)
#pragma unroll
            for (int q = 0; q < 4; q++) d2[it][nt][q] = 0.f;

#pragma unroll
    for (int kt = 0; kt < 7; kt++) {
        const int ko = kt * 8;
        uint32_t a[4][4];
#pragma unroll
        for (int it = 0; it < 4; it++) {
            const uint32_t* ap = (const uint32_t*)&SQ[(it * 16 + g) * 60 + ko + t];
            a[it][0] = ap[0]; a[it][1] = ap[8 * 60]; a[it][2] = ap[4]; a[it][3] = ap[8 * 60 + 4];
        }
        uint32_t b[4][2];
#pragma unroll
        for (int nt = 0; nt < 4; nt++) {
            const uint32_t* bp = (const uint32_t*)&Vs[(ko + t) * 40 + nt * 8 + g];
            b[nt][0] = bp[0]; b[nt][1] = bp[4 * 40];
        }
#pragma unroll
        for (int it = 0; it < 4; it++)
#pragma unroll
            for (int nt = 0; nt < 4; nt++) MMA_TF32(d2[it][nt], a[it], b[nt]);
    }

    // ---- store (tf32-rounded, k-pair-permuted cols for proj GEMM) ----
    float* obase = g_attn + (size_t)(win * NTOK) * N_PROJ + head * 32;
#pragma unroll
    for (int it = 0; it < 4; it++)
#pragma unroll
        for (int q = 0; q < 4; q++) {
            int tok = it * 16 + g + 8 * (q >> 1);
            if (tok < NTOK) {
                int w = 2 * t + (q & 1);
                int pcol = 2 * (w & 3) + (w >> 2);   // within the 8-group
                float* orow = obase + (size_t)tok * N_PROJ;
#pragma unroll
                for (int nt = 0; nt < 4; nt++)
                    orow[nt * 8 + pcol] = round_tf32(d2[it][nt][q]);
            }
        }
}

// ---------------------------------------------------------------------------
extern "C" void kernel_launch(void* const* d_in, const int* in_sizes, int n_in,
                              void* d_out, int out_size)
{
    const float* x          = (const float*)d_in[0];
    const float* qkv_w      = (const float*)d_in[1];
    const float* qkv_b      = (const float*)d_in[2];
    const float* proj_w     = (const float*)d_in[3];
    const float* proj_b     = (const float*)d_in[4];
    const float* bias_table = (const float*)d_in[5];
    float* out = (float*)d_out;

    float *qkv_p, *attn_p, *xr_p, *wtq_p, *wtp_p;
    cudaGetSymbolAddress((void**)&qkv_p,  g_qkv);
    cudaGetSymbolAddress((void**)&attn_p, g_attn);
    cudaGetSymbolAddress((void**)&xr_p,   g_xr);
    cudaGetSymbolAddress((void**)&wtq_p,  g_wtq);
    cudaGetSymbolAddress((void**)&wtp_p,  g_wtp);

    cudaFuncSetAttribute(gemm_mma<N_QKV, true, false>,
                         cudaFuncAttributeMaxDynamicSharedMemorySize, SMEM_BYTES);
    cudaFuncSetAttribute(gemm_mma<N_PROJ, false, true>,
                         cudaFuncAttributeMaxDynamicSharedMemorySize, SMEM_BYTES);

    // 0) preprocessing
    {
        int n8 = M_TOTAL * KDIM / 8;
        round_x_perm<<<(n8 + 255) / 256, 256>>>((const float4*)x, (float4*)xr_p, n8);
        transpose_round<<<dim3(N_QKV / 32, KDIM / 32), dim3(32, 8)>>>(qkv_w, wtq_p, KDIM, N_QKV);
        transpose_round<<<dim3(N_PROJ / 32, KDIM / 32), dim3(32, 8)>>>(proj_w, wtp_p, KDIM, N_PROJ);
    }
    // 1) QKV GEMM
    gemm_mma<N_QKV, true, false><<<dim3(N_QKV / BN, M_TOTAL / BM), 256, SMEM_BYTES>>>(
        xr_p, wtq_p, qkv_b, qkv_p);
    // 2) tensor-core window attention (one warp per window-head)
    attn_mma_kernel<<<NWIN * HEADS, 32>>>(bias_table);
    // 3) proj GEMM
    gemm_mma<N_PROJ, false, true><<<dim3(N_PROJ / BN, M_TOTAL / BM), 256, SMEM_BYTES>>>(
        attn_p, wtp_p, proj_b, out);
}

// round 9
// speedup vs baseline: 1.6415x; 1.5720x over previous
#include <cuda_runtime.h>
#include <cuda_fp16.h>
#include <cstdint>

// Problem constants (B=32, H=W=56, C=384, heads=12, ws=7, shift=3)
#define HEADS   12
#define WS      7
#define NTOK    49
#define NWIN    2048
#define M_TOTAL (NWIN * NTOK)   // 100352
#define N_QKV   1152
#define N_PROJ  384
#define KDIM    384

// fp16 GEMM tiling: CTA 128x128, 256 threads (8 warps, warp tile 64x32),
// BK=32 halfs (12 K-steps), 4-stage cp.async ring, LDS.64 paired fragments.
// Each 16-half k-group is stored permuted [k0,k1,k8,k9 | k2,k3,k10,k11 |
// k4,k5,k12,k13 | k6,k7,k14,k15] so u2 word t = frag pair {(2t,2t+1),(2t+8,2t+9)}.
#define BM 128
#define BN 128
#define BK 32
#define KSTEPS (KDIM / BK)        // 12
#define ROW_U2 12                 // u2 (8B) per smem row: 48 halfs (32 used + pad)
#define STAGE_U2 (BM * ROW_U2)    // 1536 u2 = 12288 B
#define NSTG 4
#define SMEM_BYTES (NSTG * 2 * STAGE_U2 * 8)   // 98304

// Scratch (__device__ globals: sanctioned allocation-free path)
__device__ __half g_qkv[(size_t)M_TOTAL * N_QKV];
__device__ __half g_attn[(size_t)M_TOTAL * N_PROJ];
__device__ __half g_xh [(size_t)M_TOTAL * KDIM];
__device__ __half g_wtq[(size_t)N_QKV * KDIM];
__device__ __half g_wtp[(size_t)N_PROJ * KDIM];

// ---------------------------------------------------------------------------
__device__ __forceinline__ int win_src_index(int m) {
    int win = m / NTOK, t = m - win * NTOK;
    int b  = win >> 6, wi = win & 63;
    int wh = wi >> 3,  ww = wi & 7;
    int r  = t / WS,   c  = t - r * WS;
    int row = wh * WS + r + 3; if (row >= 56) row -= 56;
    int col = ww * WS + c + 3; if (col >= 56) col -= 56;
    return b * 3136 + row * 56 + col;
}

__device__ __forceinline__ uint32_t smem_u32(const void* p) {
    uint32_t a;
    asm("{ .reg .u64 t; cvta.to.shared.u64 t, %1; cvt.u32.u64 %0, t; }" : "=r"(a) : "l"(p));
    return a;
}
__device__ __forceinline__ float round_tf32(float v) {
    uint32_t r;
    asm("cvt.rna.tf32.f32 %0, %1;" : "=r"(r) : "f"(v));
    return __uint_as_float(r);
}
// permuted position of k within its 16-group (see top comment)
__device__ __forceinline__ int kperm16(int k) {
    int p = (k >> 1) & 7, o = k & 1;
    return (k & ~15) + 4 * (p & 3) + 2 * (p >> 2) + o;
}

#define CP16(dst, src) \
    asm volatile("cp.async.cg.shared.global [%0], [%1], 16;" :: "r"(dst), "l"(src) : "memory")
#define CP_COMMIT() asm volatile("cp.async.commit_group;" ::: "memory")
#define CP_WAIT2()  asm volatile("cp.async.wait_group 2;" ::: "memory")
#define CP_WAIT1()  asm volatile("cp.async.wait_group 1;" ::: "memory")
#define CP_WAIT0()  asm volatile("cp.async.wait_group 0;" ::: "memory")

#define MMA_F16(c, a, b) \
    asm volatile("mma.sync.aligned.m16n8k16.row.col.f32.f16.f16.f32 " \
        "{%0,%1,%2,%3}, {%4,%5,%6,%7}, {%8,%9}, {%0,%1,%2,%3};" \
        : "+f"((c)[0]), "+f"((c)[1]), "+f"((c)[2]), "+f"((c)[3]) \
        : "r"((a)[0]), "r"((a)[1]), "r"((a)[2]), "r"((a)[3]), "r"((b)[0]), "r"((b)[1]))

#define MMA_TF32(c, a, b) \
    asm volatile("mma.sync.aligned.m16n8k8.row.col.f32.tf32.tf32.f32 " \
        "{%0,%1,%2,%3}, {%4,%5,%6,%7}, {%8,%9}, {%0,%1,%2,%3};" \
        : "+f"((c)[0]), "+f"((c)[1]), "+f"((c)[2]), "+f"((c)[3]) \
        : "r"((a)[0]), "r"((a)[1]), "r"((a)[2]), "r"((a)[3]), "r"((b)[0]), "r"((b)[1]))

// ---------------------------------------------------------------------------
// fp16 mma.sync GEMM (fp32 accum). GATHER/SCATTER fuse the roll/window map.
// CT = output element type (half for qkv, float for final proj).
template <int N_TOTAL, bool GATHER, bool SCATTER, typename CT>
__global__ void __launch_bounds__(256, 2)
gemm_h(const __half* __restrict__ A, const __half* __restrict__ WT,
       const float* __restrict__ bias, CT* __restrict__ C)
{
    extern __shared__ uint2 smu2[];
    const uint32_t smb = smem_u32(smu2);

    const int tid  = threadIdx.x;
    const int wid  = tid >> 5, lane = tid & 31;
    const int g    = lane >> 2, t = lane & 3;
    const int wm   = wid & 1, wn = wid >> 1;
    const int m0   = blockIdx.y * BM, n0 = blockIdx.x * BN;

    // loads: 2 threads per row, 16 halfs (32B = 2x CP16) each
    const int lrow = tid >> 1, lseg = (tid & 1) * 16;
    const __half* arow = A + (size_t)(GATHER ? win_src_index(m0 + lrow) : (m0 + lrow)) * KDIM + lseg;
    const __half* brow = WT + (size_t)(n0 + lrow) * KDIM + lseg;
    const uint32_t a_dst = smb + (uint32_t)lrow * 96 + lseg * 2;
    const uint32_t b_dst = a_dst + STAGE_U2 * 8;

    auto load_stage = [&](int s, int kt) {
        const uint32_t so = (uint32_t)s * (2 * STAGE_U2 * 8);
        const __half* ap = arow + kt * BK;
        const __half* bp = brow + kt * BK;
        CP16(a_dst + so,      ap);
        CP16(a_dst + so + 16, ap + 8);
        CP16(b_dst + so,      bp);
        CP16(b_dst + so + 16, bp + 8);
    };

    float c[4][4][4];
#pragma unroll
    for (int i = 0; i < 4; i++)
#pragma unroll
        for (int j = 0; j < 4; j++)
#pragma unroll
            for (int q = 0; q < 4; q++) c[i][j][q] = 0.f;

#pragma unroll
    for (int s = 0; s < NSTG - 1; s++) { load_stage(s, s); CP_COMMIT(); }

#pragma unroll 4
    for (int kt = 0; kt < KSTEPS; kt++) {
        const int rem = KSTEPS - 1 - kt;
        if (rem >= 2)      CP_WAIT2();
        else if (rem == 1) CP_WAIT1();
        else               CP_WAIT0();
        __syncthreads();

        if (kt + NSTG - 1 < KSTEPS) { load_stage((kt + NSTG - 1) & 3, kt + NSTG - 1); CP_COMMIT(); }

        const uint2* AsU2 = smu2 + (kt & 3) * (2 * STAGE_U2);
        const uint2* BsU2 = AsU2 + STAGE_U2;

#pragma unroll
        for (int ks = 0; ks < 2; ks++) {         // two k16 sub-steps per BK=32
            const int ko4 = ks * 4;
            uint32_t a[4][4];
#pragma unroll
            for (int i = 0; i < 4; i++) {
                const int r2 = (wm * 64 + i * 16 + g) * ROW_U2 + ko4 + t;
                uint2 p0 = AsU2[r2];                 // {a0, a2} row g
                uint2 p1 = AsU2[r2 + 8 * ROW_U2];    // {a1, a3} row g+8
                a[i][0] = p0.x; a[i][1] = p1.x; a[i][2] = p0.y; a[i][3] = p1.y;
            }
            uint32_t b[4][2];
#pragma unroll
            for (int j = 0; j < 4; j++) {
                const int n2 = (wn * 32 + j * 8 + g) * ROW_U2 + ko4 + t;
                uint2 q = BsU2[n2];                  // {b0, b1}
                b[j][0] = q.x; b[j][1] = q.y;
            }
#pragma unroll
            for (int i = 0; i < 4; i++)
#pragma unroll
                for (int j = 0; j < 4; j++) MMA_F16(c[i][j], a[i], b[j]);
        }
    }

    // epilogue: fp32 bias add, store CT
    const int ncolb = n0 + wn * 32;
    float2 bj[4];
#pragma unroll
    for (int j = 0; j < 4; j++)
        bj[j] = *reinterpret_cast<const float2*>(&bias[ncolb + j * 8 + 2 * t]);

#pragma unroll
    for (int i = 0; i < 4; i++) {
        const int mrow = m0 + wm * 64 + i * 16 + g;
        const size_t r0 = SCATTER ? (size_t)win_src_index(mrow)     : (size_t)mrow;
        const size_t r1 = SCATTER ? (size_t)win_src_index(mrow + 8) : (size_t)(mrow + 8);
        CT* p0 = C + r0 * N_TOTAL + ncolb + 2 * t;
        CT* p1 = C + r1 * N_TOTAL + ncolb + 2 * t;
#pragma unroll
        for (int j = 0; j < 4; j++) {
            float x0 = c[i][j][0] + bj[j].x, y0 = c[i][j][1] + bj[j].y;
            float x1 = c[i][j][2] + bj[j].x, y1 = c[i][j][3] + bj[j].y;
            if (sizeof(CT) == 2) {
                *reinterpret_cast<__half2*>(p0 + j * 8) = __floats2half2_rn(x0, y0);
                *reinterpret_cast<__half2*>(p1 + j * 8) = __floats2half2_rn(x1, y1);
            } else {
                *reinterpret_cast<float2*>(p0 + j * 8) = make_float2(x0, y0);
                *reinterpret_cast<float2*>(p1 + j * 8) = make_float2(x1, y1);
            }
        }
    }
}

// ---------------------------------------------------------------------------
// Preprocessing: W[K][N] -> WT[N][Kperm] half; x -> half (k-group permuted)
__global__ void transpose_half(const float* __restrict__ W, __half* __restrict__ WT,
                               int K, int N)
{
    __shared__ float tbuf[32][33];
    const int n0 = blockIdx.x * 32, k0 = blockIdx.y * 32;
    const int tx = threadIdx.x, ty = threadIdx.y;
#pragma unroll
    for (int i = 0; i < 4; i++)
        tbuf[ty + 8 * i][tx] = W[(size_t)(k0 + ty + 8 * i) * N + n0 + tx];
    __syncthreads();
    const int kpos = kperm16(tx);
#pragma unroll
    for (int i = 0; i < 4; i++)
        WT[(size_t)(n0 + ty + 8 * i) * K + k0 + kpos] = __float2half_rn(tbuf[tx][ty + 8 * i]);
}

// one thread per 16-float k-group
__global__ void x_to_half_perm(const float4* __restrict__ in, uint4* __restrict__ out, int n16)
{
    int i = blockIdx.x * blockDim.x + threadIdx.x;
    if (i < n16) {
        float h[16];
#pragma unroll
        for (int w = 0; w < 4; w++) {
            float4 v = in[4 * i + w];
            h[4 * w] = v.x; h[4 * w + 1] = v.y; h[4 * w + 2] = v.z; h[4 * w + 3] = v.w;
        }
        __half2 o[8];
#pragma unroll
        for (int tt = 0; tt < 4; tt++) {   // u2 word tt = {k2t,k2t+1,k2t+8,k2t+9}
            o[2 * tt]     = __floats2half2_rn(h[2 * tt],     h[2 * tt + 1]);
            o[2 * tt + 1] = __floats2half2_rn(h[2 * tt + 8], h[2 * tt + 9]);
        }
        out[2 * i]     = *reinterpret_cast<uint4*>(&o[0]);
        out[2 * i + 1] = *reinterpret_cast<uint4*>(&o[4]);
    }
}

// ---------------------------------------------------------------------------
// Tensor-core window attention (tf32 mma; f16 I/O is mantissa-exact in tf32).
__global__ void __launch_bounds__(32)
attn_mma_kernel(const float* __restrict__ bias_table)
{
    const int blk  = blockIdx.x;
    const int head = blk % HEADS;
    const int win  = blk / HEADS;
    const int lane = threadIdx.x;
    const int g = lane >> 2, t = lane & 3;

    __shared__ float SQ[64 * 60];   // Q (stride 36), later P (stride 60)
    __shared__ float Ks[56 * 36];
    __shared__ float Vs[56 * 40];
    __shared__ float Bb[224];       // bias with +-13 guard pad

    for (int i = lane; i < 224; i += 32) Bb[i] = 0.f;
    __syncwarp();
    for (int i = lane; i < 169; i += 32) Bb[13 + i] = __ldg(&bias_table[i * HEADS + head]);

    const float4 z4 = make_float4(0.f, 0.f, 0.f, 0.f);
    for (int i = lane; i < 15 * 9; i += 32)
        *reinterpret_cast<float4*>(&SQ[(49 + i / 9) * 36 + (i % 9) * 4]) = z4;
    for (int i = lane; i < 7 * 9; i += 32)
        *reinterpret_cast<float4*>(&Ks[(49 + i / 9) * 36 + (i % 9) * 4]) = z4;
    for (int i = lane; i < 7 * 10; i += 32)
        *reinterpret_cast<float4*>(&Vs[(49 + i / 10) * 40 + (i % 10) * 4]) = z4;

    // stage Q,K,V from half g_qkv (8 halfs per uint4)
    const __half* qbase = g_qkv + (size_t)(win * NTOK) * N_QKV + head * 32;
    for (int idx = lane; idx < NTOK * 4; idx += 32) {
        int row = idx >> 2, w = idx & 3;
        const uint4* p = reinterpret_cast<const uint4*>(qbase + (size_t)row * N_QKV) + w;
        uint4 uq = p[0], uk = p[48], uv = p[96];
        const __half2* hq = reinterpret_cast<const __half2*>(&uq);
        const __half2* hk = reinterpret_cast<const __half2*>(&uk);
        const __half2* hv = reinterpret_cast<const __half2*>(&uv);
#pragma unroll
        for (int s = 0; s < 4; s++) {
            float2 fq = __half22float2(hq[s]);
            float2 fk = __half22float2(hk[s]);
            float2 fv = __half22float2(hv[s]);
            SQ[row * 36 + w * 8 + 2 * s]     = fq.x;
            SQ[row * 36 + w * 8 + 2 * s + 1] = fq.y;
            Ks[row * 36 + w * 8 + 2 * s]     = fk.x;
            Ks[row * 36 + w * 8 + 2 * s + 1] = fk.y;
            Vs[row * 40 + w * 8 + 2 * s]     = fv.x;
            Vs[row * 40 + w * 8 + 2 * s + 1] = fv.y;
        }
    }
    __syncwarp();

    // NOTE: g_qkv halfs were written k-group-permuted by the qkv GEMM? No —
    // the qkv GEMM epilogue writes natural column order (permutation applies
    // only to GEMM *inputs*). Q/K/V here are natural order. The QK^T and PV
    // contractions are order-invariant anyway (same permutation on both sides
    // would also cancel).

    // ---- QK^T ----
    float c[4][7][4];
#pragma unroll
    for (int it = 0; it < 4; it++)
#pragma unroll
        for (int jt = 0; jt < 7; jt++)
#pragma unroll
            for (int q = 0; q < 4; q++) c[it][jt][q] = 0.f;

#pragma unroll
    for (int kt = 0; kt < 4; kt++) {
        const int ko = kt * 8;
        uint32_t a[4][4];
#pragma unroll
        for (int it = 0; it < 4; it++) {
            const uint32_t* ap = (const uint32_t*)&SQ[(it * 16 + g) * 36 + ko + t];
            a[it][0] = ap[0]; a[it][1] = ap[8 * 36]; a[it][2] = ap[4]; a[it][3] = ap[8 * 36 + 4];
        }
#pragma unroll
        for (int jt = 0; jt < 7; jt++) {
            const uint32_t* bp = (const uint32_t*)&Ks[(jt * 8 + g) * 36 + ko + t];
            uint32_t b[2] = { bp[0], bp[4] };
#pragma unroll
            for (int it = 0; it < 4; it++) MMA_TF32(c[it][jt], a[it], b);
        }
    }
    __syncwarp();

    // ---- masked bias add + softmax ----
    const float scale = 0.17677669529663687f;
    int  pi[8];  bool rok[8];
#pragma unroll
    for (int s = 0; s < 8; s++) {
        int tok = (s >> 1) * 16 + g + 8 * (s & 1);
        rok[s] = tok < NTOK;
        int ri = tok / 7, ci = tok - ri * 7;
        pi[s] = ri * 13 + ci + 97;
    }
    int  pj[14]; bool cok[14];
#pragma unroll
    for (int u = 0; u < 14; u++) {
        int jc = (u >> 1) * 8 + 2 * t + (u & 1);
        cok[u] = jc < NTOK;
        int rj = jc / 7, cj = jc - rj * 7;
        pj[u] = rj * 13 + cj;
    }
#pragma unroll
    for (int it = 0; it < 4; it++)
#pragma unroll
        for (int jt = 0; jt < 7; jt++)
#pragma unroll
            for (int q = 0; q < 4; q++) {
                int s = it * 2 + (q >> 1), u = jt * 2 + (q & 1);
                float sc = c[it][jt][q] * scale + Bb[pi[s] - pj[u]];
                c[it][jt][q] = (rok[s] && cok[u]) ? sc : -1e9f;
            }

#pragma unroll
    for (int s = 0; s < 8; s++) {
        const int it = s >> 1, h = s & 1;
        float m = -1e9f;
#pragma unroll
        for (int jt = 0; jt < 7; jt++) {
            m = fmaxf(m, c[it][jt][h * 2]);
            m = fmaxf(m, c[it][jt][h * 2 + 1]);
        }
        m = fmaxf(m, __shfl_xor_sync(0xffffffffu, m, 1));
        m = fmaxf(m, __shfl_xor_sync(0xffffffffu, m, 2));
        float sum = 0.f;
#pragma unroll
        for (int jt = 0; jt < 7; jt++) {
            float p0 = __expf(c[it][jt][h * 2]     - m);
            float p1 = __expf(c[it][jt][h * 2 + 1] - m);
            c[it][jt][h * 2] = p0; c[it][jt][h * 2 + 1] = p1;
            sum += p0 + p1;
        }
        sum += __shfl_xor_sync(0xffffffffu, sum, 1);
        sum += __shfl_xor_sync(0xffffffffu, sum, 2);
        const float inv = 1.0f / sum;
#pragma unroll
        for (int jt = 0; jt < 7; jt++) {
            c[it][jt][h * 2]     = round_tf32(c[it][jt][h * 2]     * inv);
            c[it][jt][h * 2 + 1] = round_tf32(c[it][jt][h * 2 + 1] * inv);
        }
    }
    __syncwarp();

    // P -> smem (stride 60)
#pragma unroll
    for (int it = 0; it < 4; it++)
#pragma unroll
        for (int jt = 0; jt < 7; jt++) {
            float* p0 = &SQ[(it * 16 + g) * 60 + jt * 8 + 2 * t];
            *reinterpret_cast<float2*>(p0)          = make_float2(c[it][jt][0], c[it][jt][1]);
            *reinterpret_cast<float2*>(p0 + 8 * 60) = make_float2(c[it][jt][2], c[it][jt][3]);
        }
    __syncwarp();

    // ---- PV ----
    float d2[4][4][4];
#pragma unroll
    for (int it = 0; it < 4; it++)
#pragma unroll
        for (int nt = 0; nt < 4; nt++)
#pragma unroll
            for (int q = 0; q < 4; q++) d2[it][nt][q] = 0.f;

#pragma unroll
    for (int kt = 0; kt < 7; kt++) {
        const int ko = kt * 8;
        uint32_t a[4][4];
#pragma unroll
        for (int it = 0; it < 4; it++) {
            const uint32_t* ap = (const uint32_t*)&SQ[(it * 16 + g) * 60 + ko + t];
            a[it][0] = ap[0]; a[it][1] = ap[8 * 60]; a[it][2] = ap[4]; a[it][3] = ap[8 * 60 + 4];
        }
        uint32_t b[4][2];
#pragma unroll
        for (int nt = 0; nt < 4; nt++) {
            const uint32_t* bp = (const uint32_t*)&Vs[(ko + t) * 40 + nt * 8 + g];
            b[nt][0] = bp[0]; b[nt][1] = bp[4 * 40];
        }
#pragma unroll
        for (int it = 0; it < 4; it++)
#pragma unroll
            for (int nt = 0; nt < 4; nt++) MMA_TF32(d2[it][nt], a[it], b[nt]);
    }

    // ---- store half, k-group-permuted (proj GEMM A operand) ----
    __half* obase = g_attn + (size_t)(win * NTOK) * N_PROJ + head * 32;
#pragma unroll
    for (int it = 0; it < 4; it++)
#pragma unroll
        for (int q = 0; q < 4; q++) {
            int tok = it * 16 + g + 8 * (q >> 1);
            if (tok < NTOK) {
                int w = 2 * t + (q & 1);
                __half* orow = obase + (size_t)tok * N_PROJ;
#pragma unroll
                for (int nt = 0; nt < 4; nt++) {
                    int d = nt * 8 + w;               // 0..31 within head slice
                    orow[kperm16(d)] = __float2half_rn(d2[it][nt][q]);
                }
            }
        }
}

// ---------------------------------------------------------------------------
extern "C" void kernel_launch(void* const* d_in, const int* in_sizes, int n_in,
                              void* d_out, int out_size)
{
    const float* x          = (const float*)d_in[0];
    const float* qkv_w      = (const float*)d_in[1];
    const float* qkv_b      = (const float*)d_in[2];
    const float* proj_w     = (const float*)d_in[3];
    const float* proj_b     = (const float*)d_in[4];
    const float* bias_table = (const float*)d_in[5];
    float* out = (float*)d_out;

    __half *qkv_p, *attn_p, *xh_p, *wtq_p, *wtp_p;
    cudaGetSymbolAddress((void**)&qkv_p,  g_qkv);
    cudaGetSymbolAddress((void**)&attn_p, g_attn);
    cudaGetSymbolAddress((void**)&xh_p,   g_xh);
    cudaGetSymbolAddress((void**)&wtq_p,  g_wtq);
    cudaGetSymbolAddress((void**)&wtp_p,  g_wtp);

    cudaFuncSetAttribute(gemm_h<N_QKV, true, false, __half>,
                         cudaFuncAttributeMaxDynamicSharedMemorySize, SMEM_BYTES);
    cudaFuncSetAttribute(gemm_h<N_PROJ, false, true, float>,
                         cudaFuncAttributeMaxDynamicSharedMemorySize, SMEM_BYTES);

    // 0) preprocessing (fp16 rna; k-group permutation; weights -> K-major)
    {
        int n16 = M_TOTAL * KDIM / 16;
        x_to_half_perm<<<(n16 + 255) / 256, 256>>>((const float4*)x, (uint4*)xh_p, n16);
        transpose_half<<<dim3(N_QKV / 32, KDIM / 32), dim3(32, 8)>>>(qkv_w, wtq_p, KDIM, N_QKV);
        transpose_half<<<dim3(N_PROJ / 32, KDIM / 32), dim3(32, 8)>>>(proj_w, wtp_p, KDIM, N_PROJ);
    }
    // 1) QKV GEMM (fp16 mma, fused window/roll gather, half output)
    gemm_h<N_QKV, true, false, __half><<<dim3(N_QKV / BN, M_TOTAL / BM), 256, SMEM_BYTES>>>(
        xh_p, wtq_p, qkv_b, qkv_p);
    // 2) tensor-core window attention
    attn_mma_kernel<<<NWIN * HEADS, 32>>>(bias_table);
    // 3) proj GEMM (fp16 mma, fused inverse roll/window scatter, float output)
    gemm_h<N_PROJ, false, true, float><<<dim3(N_PROJ / BN, M_TOTAL / BM), 256, SMEM_BYTES>>>(
        attn_p, wtp_p, proj_b, out);
}

// round 10
// speedup vs baseline: 1.8250x; 1.1118x over previous
#include <cuda_runtime.h>
#include <cuda_fp16.h>
#include <cstdint>

// Problem constants (B=32, H=W=56, C=384, heads=12, ws=7, shift=3)
#define HEADS   12
#define WS      7
#define NTOK    49
#define NWIN    2048
#define M_TOTAL (NWIN * NTOK)   // 100352
#define N_QKV   1152
#define N_PROJ  384
#define KDIM    384

// fp16 GEMM tiling (R9 known-good): CTA 128x128, 256 threads, BK=32 halfs,
// 4-stage cp.async ring, LDS.64 paired fragments via 16-half k-group permutation
// [k0,k1,k8,k9 | k2,k3,k10,k11 | k4,k5,k12,k13 | k6,k7,k14,k15].
#define BM 128
#define BN 128
#define BK 32
#define KSTEPS (KDIM / BK)        // 12
#define ROW_U2 12                 // u2 (8B) per smem row
#define STAGE_U2 (BM * ROW_U2)
#define NSTG 4
#define SMEM_BYTES (NSTG * 2 * STAGE_U2 * 8)   // 98304

// Scratch (__device__ globals: sanctioned allocation-free path)
__device__ __half g_qkv[(size_t)M_TOTAL * N_QKV];
__device__ __half g_attn[(size_t)M_TOTAL * N_PROJ];
__device__ __half g_xh [(size_t)M_TOTAL * KDIM];
__device__ __half g_wtq[(size_t)N_QKV * KDIM];
__device__ __half g_wtp[(size_t)N_PROJ * KDIM];

// ---------------------------------------------------------------------------
__device__ __forceinline__ int win_src_index(int m) {
    int win = m / NTOK, t = m - win * NTOK;
    int b  = win >> 6, wi = win & 63;
    int wh = wi >> 3,  ww = wi & 7;
    int r  = t / WS,   c  = t - r * WS;
    int row = wh * WS + r + 3; if (row >= 56) row -= 56;
    int col = ww * WS + c + 3; if (col >= 56) col -= 56;
    return b * 3136 + row * 56 + col;
}

__device__ __forceinline__ uint32_t smem_u32(const void* p) {
    uint32_t a;
    asm("{ .reg .u64 t; cvta.to.shared.u64 t, %1; cvt.u32.u64 %0, t; }" : "=r"(a) : "l"(p));
    return a;
}
// permuted position of k within its 16-group
__device__ __forceinline__ int kperm16(int k) {
    int p = (k >> 1) & 7, o = k & 1;
    return (k & ~15) + 4 * (p & 3) + 2 * (p >> 2) + o;
}

#define CP16(dst, src) \
    asm volatile("cp.async.cg.shared.global [%0], [%1], 16;" :: "r"(dst), "l"(src) : "memory")
#define CP_COMMIT() asm volatile("cp.async.commit_group;" ::: "memory")
#define CP_WAIT2()  asm volatile("cp.async.wait_group 2;" ::: "memory")
#define CP_WAIT1()  asm volatile("cp.async.wait_group 1;" ::: "memory")
#define CP_WAIT0()  asm volatile("cp.async.wait_group 0;" ::: "memory")

#define MMA_F16(c, a, b) \
    asm volatile("mma.sync.aligned.m16n8k16.row.col.f32.f16.f16.f32 " \
        "{%0,%1,%2,%3}, {%4,%5,%6,%7}, {%8,%9}, {%0,%1,%2,%3};" \
        : "+f"((c)[0]), "+f"((c)[1]), "+f"((c)[2]), "+f"((c)[3]) \
        : "r"((a)[0]), "r"((a)[1]), "r"((a)[2]), "r"((a)[3]), "r"((b)[0]), "r"((b)[1]))

// ---------------------------------------------------------------------------
// fp16 mma.sync GEMM (fp32 accum), R9 loop verbatim.
template <int N_TOTAL, bool GATHER, bool SCATTER, typename CT>
__global__ void __launch_bounds__(256, 2)
gemm_h(const __half* __restrict__ A, const __half* __restrict__ WT,
       const float* __restrict__ bias, CT* __restrict__ C)
{
    extern __shared__ uint2 smu2[];
    const uint32_t smb = smem_u32(smu2);

    const int tid  = threadIdx.x;
    const int wid  = tid >> 5, lane = tid & 31;
    const int g    = lane >> 2, t = lane & 3;
    const int wm   = wid & 1, wn = wid >> 1;
    const int m0   = blockIdx.y * BM, n0 = blockIdx.x * BN;

    const int lrow = tid >> 1, lseg = (tid & 1) * 16;
    const __half* arow = A + (size_t)(GATHER ? win_src_index(m0 + lrow) : (m0 + lrow)) * KDIM + lseg;
    const __half* brow = WT + (size_t)(n0 + lrow) * KDIM + lseg;
    const uint32_t a_dst = smb + (uint32_t)lrow * 96 + lseg * 2;
    const uint32_t b_dst = a_dst + STAGE_U2 * 8;

    auto load_stage = [&](int s, int kt) {
        const uint32_t so = (uint32_t)s * (2 * STAGE_U2 * 8);
        const __half* ap = arow + kt * BK;
        const __half* bp = brow + kt * BK;
        CP16(a_dst + so,      ap);
        CP16(a_dst + so + 16, ap + 8);
        CP16(b_dst + so,      bp);
        CP16(b_dst + so + 16, bp + 8);
    };

    float c[4][4][4];
#pragma unroll
    for (int i = 0; i < 4; i++)
#pragma unroll
        for (int j = 0; j < 4; j++)
#pragma unroll
            for (int q = 0; q < 4; q++) c[i][j][q] = 0.f;

#pragma unroll
    for (int s = 0; s < NSTG - 1; s++) { load_stage(s, s); CP_COMMIT(); }

#pragma unroll 4
    for (int kt = 0; kt < KSTEPS; kt++) {
        const int rem = KSTEPS - 1 - kt;
        if (rem >= 2)      CP_WAIT2();
        else if (rem == 1) CP_WAIT1();
        else               CP_WAIT0();
        __syncthreads();

        if (kt + NSTG - 1 < KSTEPS) { load_stage((kt + NSTG - 1) & 3, kt + NSTG - 1); CP_COMMIT(); }

        const uint2* AsU2 = smu2 + (kt & 3) * (2 * STAGE_U2);
        const uint2* BsU2 = AsU2 + STAGE_U2;

#pragma unroll
        for (int ks = 0; ks < 2; ks++) {
            const int ko4 = ks * 4;
            uint32_t a[4][4];
#pragma unroll
            for (int i = 0; i < 4; i++) {
                const int r2 = (wm * 64 + i * 16 + g) * ROW_U2 + ko4 + t;
                uint2 p0 = AsU2[r2];
                uint2 p1 = AsU2[r2 + 8 * ROW_U2];
                a[i][0] = p0.x; a[i][1] = p1.x; a[i][2] = p0.y; a[i][3] = p1.y;
            }
            uint32_t b[4][2];
#pragma unroll
            for (int j = 0; j < 4; j++) {
                const int n2 = (wn * 32 + j * 8 + g) * ROW_U2 + ko4 + t;
                uint2 q = BsU2[n2];
                b[j][0] = q.x; b[j][1] = q.y;
            }
#pragma unroll
            for (int i = 0; i < 4; i++)
#pragma unroll
                for (int j = 0; j < 4; j++) MMA_F16(c[i][j], a[i], b[j]);
        }
    }

    const int ncolb = n0 + wn * 32;
    float2 bj[4];
#pragma unroll
    for (int j = 0; j < 4; j++)
        bj[j] = *reinterpret_cast<const float2*>(&bias[ncolb + j * 8 + 2 * t]);

#pragma unroll
    for (int i = 0; i < 4; i++) {
        const int mrow = m0 + wm * 64 + i * 16 + g;
        const size_t r0 = SCATTER ? (size_t)win_src_index(mrow)     : (size_t)mrow;
        const size_t r1 = SCATTER ? (size_t)win_src_index(mrow + 8) : (size_t)(mrow + 8);
        CT* p0 = C + r0 * N_TOTAL + ncolb + 2 * t;
        CT* p1 = C + r1 * N_TOTAL + ncolb + 2 * t;
#pragma unroll
        for (int j = 0; j < 4; j++) {
            float x0 = c[i][j][0] + bj[j].x, y0 = c[i][j][1] + bj[j].y;
            float x1 = c[i][j][2] + bj[j].x, y1 = c[i][j][3] + bj[j].y;
            if (sizeof(CT) == 2) {
                *reinterpret_cast<__half2*>(p0 + j * 8) = __floats2half2_rn(x0, y0);
                *reinterpret_cast<__half2*>(p1 + j * 8) = __floats2half2_rn(x1, y1);
            } else {
                *reinterpret_cast<float2*>(p0 + j * 8) = make_float2(x0, y0);
                *reinterpret_cast<float2*>(p1 + j * 8) = make_float2(x1, y1);
            }
        }
    }
}

// ---------------------------------------------------------------------------
// Preprocessing (R9 verbatim)
__global__ void transpose_half(const float* __restrict__ W, __half* __restrict__ WT,
                               int K, int N)
{
    __shared__ float tbuf[32][33];
    const int n0 = blockIdx.x * 32, k0 = blockIdx.y * 32;
    const int tx = threadIdx.x, ty = threadIdx.y;
#pragma unroll
    for (int i = 0; i < 4; i++)
        tbuf[ty + 8 * i][tx] = W[(size_t)(k0 + ty + 8 * i) * N + n0 + tx];
    __syncthreads();
    const int kpos = kperm16(tx);
#pragma unroll
    for (int i = 0; i < 4; i++)
        WT[(size_t)(n0 + ty + 8 * i) * K + k0 + kpos] = __float2half_rn(tbuf[tx][ty + 8 * i]);
}

__global__ void x_to_half_perm(const float4* __restrict__ in, uint4* __restrict__ out, int n16)
{
    int i = blockIdx.x * blockDim.x + threadIdx.x;
    if (i < n16) {
        float h[16];
#pragma unroll
        for (int w = 0; w < 4; w++) {
            float4 v = in[4 * i + w];
            h[4 * w] = v.x; h[4 * w + 1] = v.y; h[4 * w + 2] = v.z; h[4 * w + 3] = v.w;
        }
        __half2 o[8];
#pragma unroll
        for (int tt = 0; tt < 4; tt++) {
            o[2 * tt]     = __floats2half2_rn(h[2 * tt],     h[2 * tt + 1]);
            o[2 * tt + 1] = __floats2half2_rn(h[2 * tt + 8], h[2 * tt + 9]);
        }
        out[2 * i]     = *reinterpret_cast<uint4*>(&o[0]);
        out[2 * i + 1] = *reinterpret_cast<uint4*>(&o[4]);
    }
}

// ---------------------------------------------------------------------------
// fp16 flash-style window attention: one warp per (window, head).
// QK^T: m16n8k16 fp16 (56 HMMA); softmax in fp32 on accumulators; P converted
// in-register to PV A-fragments (accumulator layout == A-fragment layout);
// PV: m16n8k16 fp16 against V^T staged [dim][token] (64 HMMA). ~15.5KB smem.
__global__ void __launch_bounds__(32)
attn_h_kernel(const float* __restrict__ bias_table)
{
    const int head = blockIdx.x % HEADS;
    const int win  = blockIdx.x / HEADS;
    const int lane = threadIdx.x;
    const int g = lane >> 2, t = lane & 3;

    __shared__ __half SQ[64 * 40];   // [token][dim], stride 40 halfs
    __shared__ __half SK[64 * 40];
    __shared__ __half SVt[32 * 72];  // [dim][token], stride 72 halfs
    __shared__ float  Bb[224];       // bias, +-13 guard pad: index 13+rel

    // bias staging
    for (int i = lane; i < 224; i += 32) Bb[i] = 0.f;
    __syncwarp();
    for (int i = lane; i < 169; i += 32) Bb[13 + i] = __ldg(&bias_table[i * HEADS + head]);

    // zero SVt (pad tokens MUST be 0: P=0 x garbage=NaN hazard in PV)
    {
        const uint4 z = make_uint4(0, 0, 0, 0);
        uint4* v4 = reinterpret_cast<uint4*>(SVt);
        for (int i = lane; i < 32 * 72 * 2 / 16; i += 32) v4[i] = z;
    }
    __syncwarp();

    // stage Q,K (raw fp16 copies) and V transposed
    const __half* qbase = g_qkv + (size_t)(win * NTOK) * N_QKV + head * 32;
    for (int idx = lane; idx < NTOK * 4; idx += 32) {
        int row = idx >> 2, w = idx & 3;
        const uint4* p = reinterpret_cast<const uint4*>(qbase + (size_t)row * N_QKV) + w;
        uint4 uq = p[0], uk = p[48], uv = p[96];
        *reinterpret_cast<uint4*>(&SQ[row * 40 + w * 8]) = uq;
        *reinterpret_cast<uint4*>(&SK[row * 40 + w * 8]) = uk;
        const __half* hv = reinterpret_cast<const __half*>(&uv);
#pragma unroll
        for (int s = 0; s < 8; s++)
            SVt[(w * 8 + s) * 72 + row] = hv[s];
    }
    __syncwarp();

    // ---- QK^T (fp16, K=32 -> 2 k16 steps) ----
    float c[4][7][4];
#pragma unroll
    for (int it = 0; it < 4; it++)
#pragma unroll
        for (int jt = 0; jt < 7; jt++)
#pragma unroll
            for (int q = 0; q < 4; q++) c[it][jt][q] = 0.f;

#pragma unroll
    for (int kt = 0; kt < 2; kt++) {
        const int ko = kt * 16;
        uint32_t a[4][4];
#pragma unroll
        for (int it = 0; it < 4; it++) {
            a[it][0] = *reinterpret_cast<const uint32_t*>(&SQ[(it * 16 + g)     * 40 + ko + 2 * t]);
            a[it][1] = *reinterpret_cast<const uint32_t*>(&SQ[(it * 16 + g + 8) * 40 + ko + 2 * t]);
            a[it][2] = *reinterpret_cast<const uint32_t*>(&SQ[(it * 16 + g)     * 40 + ko + 8 + 2 * t]);
            a[it][3] = *reinterpret_cast<const uint32_t*>(&SQ[(it * 16 + g + 8) * 40 + ko + 8 + 2 * t]);
        }
#pragma unroll
        for (int jt = 0; jt < 7; jt++) {
            uint32_t b[2];
            b[0] = *reinterpret_cast<const uint32_t*>(&SK[(jt * 8 + g) * 40 + ko + 2 * t]);
            b[1] = *reinterpret_cast<const uint32_t*>(&SK[(jt * 8 + g) * 40 + ko + 8 + 2 * t]);
#pragma unroll
            for (int it = 0; it < 4; it++) MMA_F16(c[it][jt], a[it], b);
        }
    }

    // ---- masked bias add + softmax (fp32, in accumulators) ----
    const float scale = 0.17677669529663687f;
    int  pi[8];  bool rok[8];
#pragma unroll
    for (int s = 0; s < 8; s++) {
        int tok = (s >> 1) * 16 + g + 8 * (s & 1);
        rok[s] = tok < NTOK;
        int ri = tok / 7, ci = tok - ri * 7;
        pi[s] = ri * 13 + ci + 97;
    }
    int  pj[14]; bool cok[14];
#pragma unroll
    for (int u = 0; u < 14; u++) {
        int jc = (u >> 1) * 8 + 2 * t + (u & 1);
        cok[u] = jc < NTOK;
        int rj = jc / 7, cj = jc - rj * 7;
        pj[u] = rj * 13 + cj;
    }
#pragma unroll
    for (int it = 0; it < 4; it++)
#pragma unroll
        for (int jt = 0; jt < 7; jt++)
#pragma unroll
            for (int q = 0; q < 4; q++) {
                int s = it * 2 + (q >> 1), u = jt * 2 + (q & 1);
                float sc = c[it][jt][q] * scale + Bb[pi[s] - pj[u]];
                c[it][jt][q] = (rok[s] && cok[u]) ? sc : -1e9f;
            }

#pragma unroll
    for (int s = 0; s < 8; s++) {
        const int it = s >> 1, h = s & 1;
        float m = -1e9f;
#pragma unroll
        for (int jt = 0; jt < 7; jt++) {
            m = fmaxf(m, c[it][jt][h * 2]);
            m = fmaxf(m, c[it][jt][h * 2 + 1]);
        }
        m = fmaxf(m, __shfl_xor_sync(0xffffffffu, m, 1));
        m = fmaxf(m, __shfl_xor_sync(0xffffffffu, m, 2));
        float sum = 0.f;
#pragma unroll
        for (int jt = 0; jt < 7; jt++) {
            float p0 = __expf(c[it][jt][h * 2]     - m);
            float p1 = __expf(c[it][jt][h * 2 + 1] - m);
            c[it][jt][h * 2] = p0; c[it][jt][h * 2 + 1] = p1;
            sum += p0 + p1;
        }
        sum += __shfl_xor_sync(0xffffffffu, sum, 1);
        sum += __shfl_xor_sync(0xffffffffu, sum, 2);
        const float inv = 1.0f / sum;
#pragma unroll
        for (int jt = 0; jt < 7; jt++) {
            c[it][jt][h * 2]     *= inv;
            c[it][jt][h * 2 + 1] *= inv;
        }
    }

    // ---- P: accumulators -> fp16 A-fragments in registers (no smem pass) ----
    // A frag (it, kt): reg0=(g, k=16kt+2t..+1), reg1=(g+8, same), reg2=(g, +8), reg3=(g+8, +8)
    uint32_t pa[4][4][4];
#pragma unroll
    for (int it = 0; it < 4; it++)
#pragma unroll
        for (int kt = 0; kt < 4; kt++) {
            const int jt0 = 2 * kt, jt1 = 2 * kt + 1;
            pa[it][kt][0] = __half2_raw(__floats2half2_rn(c[it][jt0][0], c[it][jt0][1])).x
                            | ((uint32_t)__half2_raw(__floats2half2_rn(c[it][jt0][0], c[it][jt0][1])).y << 16);
            // simpler: reinterpret
            __half2 h0 = __floats2half2_rn(c[it][jt0][0], c[it][jt0][1]);
            __half2 h1 = __floats2half2_rn(c[it][jt0][2], c[it][jt0][3]);
            pa[it][kt][0] = *reinterpret_cast<uint32_t*>(&h0);
            pa[it][kt][1] = *reinterpret_cast<uint32_t*>(&h1);
            if (jt1 < 7) {
                __half2 h2 = __floats2half2_rn(c[it][jt1][0], c[it][jt1][1]);
                __half2 h3 = __floats2half2_rn(c[it][jt1][2], c[it][jt1][3]);
                pa[it][kt][2] = *reinterpret_cast<uint32_t*>(&h2);
                pa[it][kt][3] = *reinterpret_cast<uint32_t*>(&h3);
            } else {
                pa[it][kt][2] = 0u;
                pa[it][kt][3] = 0u;
            }
        }

    // ---- PV (fp16, K=64 incl. zero pad -> 4 k16 steps) ----
    float d[4][4][4];
#pragma unroll
    for (int it = 0; it < 4; it++)
#pragma unroll
        for (int nt = 0; nt < 4; nt++)
#pragma unroll
            for (int q = 0; q < 4; q++) d[it][nt][q] = 0.f;

#pragma unroll
    for (int kt = 0; kt < 4; kt++) {
        const int ko = kt * 16;
        uint32_t b[4][2];
#pragma unroll
        for (int nt = 0; nt < 4; nt++) {
            b[nt][0] = *reinterpret_cast<const uint32_t*>(&SVt[(nt * 8 + g) * 72 + ko + 2 * t]);
            b[nt][1] = *reinterpret_cast<const uint32_t*>(&SVt[(nt * 8 + g) * 72 + ko + 8 + 2 * t]);
        }
#pragma unroll
        for (int it = 0; it < 4; it++)
#pragma unroll
            for (int nt = 0; nt < 4; nt++) MMA_F16(d[it][nt], pa[it][kt], b[nt]);
    }

    // ---- store half, k-group-permuted (proj GEMM A operand) ----
    __half* obase = g_attn + (size_t)(win * NTOK) * N_PROJ + head * 32;
#pragma unroll
    for (int it = 0; it < 4; it++)
#pragma unroll
        for (int q = 0; q < 4; q++) {
            int tok = it * 16 + g + 8 * (q >> 1);
            if (tok < NTOK) {
                int w = 2 * t + (q & 1);
                __half* orow = obase + (size_t)tok * N_PROJ;
#pragma unroll
                for (int nt = 0; nt < 4; nt++) {
                    int dcol = nt * 8 + w;
                    orow[kperm16(dcol)] = __float2half_rn(d[it][nt][q]);
                }
            }
        }
}

// ---------------------------------------------------------------------------
extern "C" void kernel_launch(void* const* d_in, const int* in_sizes, int n_in,
                              void* d_out, int out_size)
{
    const float* x          = (const float*)d_in[0];
    const float* qkv_w      = (const float*)d_in[1];
    const float* qkv_b      = (const float*)d_in[2];
    const float* proj_w     = (const float*)d_in[3];
    const float* proj_b     = (const float*)d_in[4];
    const float* bias_table = (const float*)d_in[5];
    float* out = (float*)d_out;

    __half *qkv_p, *attn_p, *xh_p, *wtq_p, *wtp_p;
    cudaGetSymbolAddress((void**)&qkv_p,  g_qkv);
    cudaGetSymbolAddress((void**)&attn_p, g_attn);
    cudaGetSymbolAddress((void**)&xh_p,   g_xh);
    cudaGetSymbolAddress((void**)&wtq_p,  g_wtq);
    cudaGetSymbolAddress((void**)&wtp_p,  g_wtp);

    cudaFuncSetAttribute(gemm_h<N_QKV, true, false, __half>,
                         cudaFuncAttributeMaxDynamicSharedMemorySize, SMEM_BYTES);
    cudaFuncSetAttribute(gemm_h<N_PROJ, false, true, float>,
                         cudaFuncAttributeMaxDynamicSharedMemorySize, SMEM_BYTES);

    // 0) preprocessing
    {
        int n16 = M_TOTAL * KDIM / 16;
        x_to_half_perm<<<(n16 + 255) / 256, 256>>>((const float4*)x, (uint4*)xh_p, n16);
        transpose_half<<<dim3(N_QKV / 32, KDIM / 32), dim3(32, 8)>>>(qkv_w, wtq_p, KDIM, N_QKV);
        transpose_half<<<dim3(N_PROJ / 32, KDIM / 32), dim3(32, 8)>>>(proj_w, wtp_p, KDIM, N_PROJ);
    }
    // 1) QKV GEMM (fp16 mma, fused window/roll gather)
    gemm_h<N_QKV, true, false, __half><<<dim3(N_QKV / BN, M_TOTAL / BM), 256, SMEM_BYTES>>>(
        xh_p, wtq_p, qkv_b, qkv_p);
    // 2) fp16 flash-style window attention
    attn_h_kernel<<<NWIN * HEADS, 32>>>(bias_table);
    // 3) proj GEMM (fp16 mma, fused inverse roll/window scatter)
    gemm_h<N_PROJ, false, true, float><<<dim3(N_PROJ / BN, M_TOTAL / BM), 256, SMEM_BYTES>>>(
        attn_p, wtp_p, proj_b, out);
}

// round 11
// speedup vs baseline: 2.1156x; 1.1592x over previous
#include <cuda_runtime.h>
#include <cuda_fp16.h>
#include <cstdint>

// Problem constants (B=32, H=W=56, C=384, heads=12, ws=7, shift=3)
#define HEADS   12
#define WS      7
#define NTOK    49
#define NWIN    2048
#define M_TOTAL (NWIN * NTOK)   // 100352
#define N_QKV   1152
#define N_PROJ  384
#define KDIM    384

// fp16 GEMM tiling (R9/R10 known-good): CTA 128x128, 256 threads, BK=32 halfs,
// 4-stage cp.async ring, LDS.64 paired fragments via 16-half k-group permutation
// [k0,k1,k8,k9 | k2,k3,k10,k11 | k4,k5,k12,k13 | k6,k7,k14,k15].
#define BM 128
#define BN 128
#define BK 32
#define KSTEPS (KDIM / BK)        // 12
#define ROW_U2 12                 // u2 (8B) per smem row
#define STAGE_U2 (BM * ROW_U2)
#define NSTG 4
#define SMEM_BYTES (NSTG * 2 * STAGE_U2 * 8)   // 98304

// Scratch. g_qkv holds qkv output in HEAD-MAJOR layout: 36 slabs
// [tensor*12+head][m][32] so attention reads are contiguous per (win,head).
__device__ __half g_qkv[(size_t)M_TOTAL * N_QKV];
__device__ __half g_attn[(size_t)M_TOTAL * N_PROJ];
__device__ __half g_xh [(size_t)M_TOTAL * KDIM];
__device__ __half g_wtq[(size_t)N_QKV * KDIM];
__device__ __half g_wtp[(size_t)N_PROJ * KDIM];

// ---------------------------------------------------------------------------
__device__ __forceinline__ int win_src_index(int m) {
    int win = m / NTOK, t = m - win * NTOK;
    int b  = win >> 6, wi = win & 63;
    int wh = wi >> 3,  ww = wi & 7;
    int r  = t / WS,   c  = t - r * WS;
    int row = wh * WS + r + 3; if (row >= 56) row -= 56;
    int col = ww * WS + c + 3; if (col >= 56) col -= 56;
    return b * 3136 + row * 56 + col;
}

__device__ __forceinline__ uint32_t smem_u32(const void* p) {
    uint32_t a;
    asm("{ .reg .u64 t; cvta.to.shared.u64 t, %1; cvt.u32.u64 %0, t; }" : "=r"(a) : "l"(p));
    return a;
}
// permuted position of k within its 16-group
__device__ __forceinline__ int kperm16(int k) {
    int p = (k >> 1) & 7, o = k & 1;
    return (k & ~15) + 4 * (p & 3) + 2 * (p >> 2) + o;
}

#define CP16(dst, src) \
    asm volatile("cp.async.cg.shared.global [%0], [%1], 16;" :: "r"(dst), "l"(src) : "memory")
#define CP_COMMIT() asm volatile("cp.async.commit_group;" ::: "memory")
#define CP_WAIT2()  asm volatile("cp.async.wait_group 2;" ::: "memory")
#define CP_WAIT1()  asm volatile("cp.async.wait_group 1;" ::: "memory")
#define CP_WAIT0()  asm volatile("cp.async.wait_group 0;" ::: "memory")

#define MMA_F16(c, a, b) \
    asm volatile("mma.sync.aligned.m16n8k16.row.col.f32.f16.f16.f32 " \
        "{%0,%1,%2,%3}, {%4,%5,%6,%7}, {%8,%9}, {%0,%1,%2,%3};" \
        : "+f"((c)[0]), "+f"((c)[1]), "+f"((c)[2]), "+f"((c)[3]) \
        : "r"((a)[0]), "r"((a)[1]), "r"((a)[2]), "r"((a)[3]), "r"((b)[0]), "r"((b)[1]))

// ---------------------------------------------------------------------------
// fp16 mma.sync GEMM (fp32 accum), R9 mainloop verbatim.
// HEADOUT: write C in [ncol/32][m][32] slab layout (qkv -> attention handoff).
// SCATTER: fuse inverse roll/window into output rows (proj).
template <int N_TOTAL, bool GATHER, bool SCATTER, bool HEADOUT, typename CT>
__global__ void __launch_bounds__(256, 2)
gemm_h(const __half* __restrict__ A, const __half* __restrict__ WT,
       const float* __restrict__ bias, CT* __restrict__ C)
{
    extern __shared__ uint2 smu2[];
    const uint32_t smb = smem_u32(smu2);

    const int tid  = threadIdx.x;
    const int wid  = tid >> 5, lane = tid & 31;
    const int g    = lane >> 2, t = lane & 3;
    const int wm   = wid & 1, wn = wid >> 1;
    const int m0   = blockIdx.y * BM, n0 = blockIdx.x * BN;

    const int lrow = tid >> 1, lseg = (tid & 1) * 16;
    const __half* arow = A + (size_t)(GATHER ? win_src_index(m0 + lrow) : (m0 + lrow)) * KDIM + lseg;
    const __half* brow = WT + (size_t)(n0 + lrow) * KDIM + lseg;
    const uint32_t a_dst = smb + (uint32_t)lrow * 96 + lseg * 2;
    const uint32_t b_dst = a_dst + STAGE_U2 * 8;

    auto load_stage = [&](int s, int kt) {
        const uint32_t so = (uint32_t)s * (2 * STAGE_U2 * 8);
        const __half* ap = arow + kt * BK;
        const __half* bp = brow + kt * BK;
        CP16(a_dst + so,      ap);
        CP16(a_dst + so + 16, ap + 8);
        CP16(b_dst + so,      bp);
        CP16(b_dst + so + 16, bp + 8);
    };

    float c[4][4][4];
#pragma unroll
    for (int i = 0; i < 4; i++)
#pragma unroll
        for (int j = 0; j < 4; j++)
#pragma unroll
            for (int q = 0; q < 4; q++) c[i][j][q] = 0.f;

#pragma unroll
    for (int s = 0; s < NSTG - 1; s++) { load_stage(s, s); CP_COMMIT(); }

#pragma unroll 4
    for (int kt = 0; kt < KSTEPS; kt++) {
        const int rem = KSTEPS - 1 - kt;
        if (rem >= 2)      CP_WAIT2();
        else if (rem == 1) CP_WAIT1();
        else               CP_WAIT0();
        __syncthreads();

        if (kt + NSTG - 1 < KSTEPS) { load_stage((kt + NSTG - 1) & 3, kt + NSTG - 1); CP_COMMIT(); }

        const uint2* AsU2 = smu2 + (kt & 3) * (2 * STAGE_U2);
        const uint2* BsU2 = AsU2 + STAGE_U2;

#pragma unroll
        for (int ks = 0; ks < 2; ks++) {
            const int ko4 = ks * 4;
            uint32_t a[4][4];
#pragma unroll
            for (int i = 0; i < 4; i++) {
                const int r2 = (wm * 64 + i * 16 + g) * ROW_U2 + ko4 + t;
                uint2 p0 = AsU2[r2];
                uint2 p1 = AsU2[r2 + 8 * ROW_U2];
                a[i][0] = p0.x; a[i][1] = p1.x; a[i][2] = p0.y; a[i][3] = p1.y;
            }
            uint32_t b[4][2];
#pragma unroll
            for (int j = 0; j < 4; j++) {
                const int n2 = (wn * 32 + j * 8 + g) * ROW_U2 + ko4 + t;
                uint2 q = BsU2[n2];
                b[j][0] = q.x; b[j][1] = q.y;
            }
#pragma unroll
            for (int i = 0; i < 4; i++)
#pragma unroll
                for (int j = 0; j < 4; j++) MMA_F16(c[i][j], a[i], b[j]);
        }
    }

    const int ncolb = n0 + wn * 32;
    float2 bj[4];
#pragma unroll
    for (int j = 0; j < 4; j++)
        bj[j] = *reinterpret_cast<const float2*>(&bias[ncolb + j * 8 + 2 * t]);

#pragma unroll
    for (int i = 0; i < 4; i++) {
        const int mrow = m0 + wm * 64 + i * 16 + g;
        CT *p0, *p1;
        if (HEADOUT) {
            const size_t slab = (size_t)(ncolb >> 5) * M_TOTAL;
            p0 = C + (slab + mrow)     * 32 + 2 * t;
            p1 = C + (slab + mrow + 8) * 32 + 2 * t;
        } else {
            const size_t r0 = SCATTER ? (size_t)win_src_index(mrow)     : (size_t)mrow;
            const size_t r1 = SCATTER ? (size_t)win_src_index(mrow + 8) : (size_t)(mrow + 8);
            p0 = C + r0 * N_TOTAL + ncolb + 2 * t;
            p1 = C + r1 * N_TOTAL + ncolb + 2 * t;
        }
#pragma unroll
        for (int j = 0; j < 4; j++) {
            float x0 = c[i][j][0] + bj[j].x, y0 = c[i][j][1] + bj[j].y;
            float x1 = c[i][j][2] + bj[j].x, y1 = c[i][j][3] + bj[j].y;
            if (sizeof(CT) == 2) {
                *reinterpret_cast<__half2*>(p0 + j * 8) = __floats2half2_rn(x0, y0);
                *reinterpret_cast<__half2*>(p1 + j * 8) = __floats2half2_rn(x1, y1);
            } else {
                *reinterpret_cast<float2*>(p0 + j * 8) = make_float2(x0, y0);
                *reinterpret_cast<float2*>(p1 + j * 8) = make_float2(x1, y1);
            }
        }
    }
}

// ---------------------------------------------------------------------------
// Preprocessing (unchanged)
__global__ void transpose_half(const float* __restrict__ W, __half* __restrict__ WT,
                               int K, int N)
{
    __shared__ float tbuf[32][33];
    const int n0 = blockIdx.x * 32, k0 = blockIdx.y * 32;
    const int tx = threadIdx.x, ty = threadIdx.y;
#pragma unroll
    for (int i = 0; i < 4; i++)
        tbuf[ty + 8 * i][tx] = W[(size_t)(k0 + ty + 8 * i) * N + n0 + tx];
    __syncthreads();
    const int kpos = kperm16(tx);
#pragma unroll
    for (int i = 0; i < 4; i++)
        WT[(size_t)(n0 + ty + 8 * i) * K + k0 + kpos] = __float2half_rn(tbuf[tx][ty + 8 * i]);
}

__global__ void x_to_half_perm(const float4* __restrict__ in, uint4* __restrict__ out, int n16)
{
    int i = blockIdx.x * blockDim.x + threadIdx.x;
    if (i < n16) {
        float h[16];
#pragma unroll
        for (int w = 0; w < 4; w++) {
            float4 v = in[4 * i + w];
            h[4 * w] = v.x; h[4 * w + 1] = v.y; h[4 * w + 2] = v.z; h[4 * w + 3] = v.w;
        }
        __half2 o[8];
#pragma unroll
        for (int tt = 0; tt < 4; tt++) {
            o[2 * tt]     = __floats2half2_rn(h[2 * tt],     h[2 * tt + 1]);
            o[2 * tt + 1] = __floats2half2_rn(h[2 * tt + 8], h[2 * tt + 9]);
        }
        out[2 * i]     = *reinterpret_cast<uint4*>(&o[0]);
        out[2 * i + 1] = *reinterpret_cast<uint4*>(&o[4]);
    }
}

// ---------------------------------------------------------------------------
// fp16 flash-style window attention, coalesced edition: one warp per (win,head).
// Q/K/V are contiguous 3136B slabs in the head-major g_qkv layout, staged with
// cp.async. V transposed in smem. P converted in-register to PV A-fragments.
__global__ void __launch_bounds__(32)
attn_h_kernel(const float* __restrict__ bias_table)
{
    const int head = blockIdx.x % HEADS;
    const int win  = blockIdx.x / HEADS;
    const int lane = threadIdx.x;
    const int g = lane >> 2, t = lane & 3;

    __shared__ __half SQ[64 * 40];   // [token][dim], stride 40 halfs
    __shared__ __half SK[56 * 40];
    __shared__ __half SVr[49 * 40];  // V rows staging
    __shared__ __half SVt[32 * 72];  // [dim][token], stride 72 halfs
    __shared__ float  Bb[224];       // bias, +-13 guard pad: index 13+rel

    // bias staging
    for (int i = lane; i < 224; i += 32) Bb[i] = 0.f;
    __syncwarp();
    for (int i = lane; i < 169; i += 32) Bb[13 + i] = __ldg(&bias_table[i * HEADS + head]);

    // zero SVt (pad tokens MUST be 0: P x garbage = NaN hazard in PV)
    {
        const uint4 z = make_uint4(0, 0, 0, 0);
        uint4* v4 = reinterpret_cast<uint4*>(SVt);
        for (int i = lane; i < 32 * 72 * 2 / 16; i += 32) v4[i] = z;
    }

    // coalesced staging: 49 rows x 64B per tensor via cp.async
    const size_t mb = (size_t)win * NTOK;
    const __half* qs = g_qkv + ((size_t)(0 * HEADS + head) * M_TOTAL + mb) * 32;
    const __half* ks = g_qkv + ((size_t)(1 * HEADS + head) * M_TOTAL + mb) * 32;
    const __half* vs = g_qkv + ((size_t)(2 * HEADS + head) * M_TOTAL + mb) * 32;
    const uint32_t sq = smem_u32(SQ), sk = smem_u32(SK), sv = smem_u32(SVr);
    for (int i = lane; i < NTOK * 4; i += 32) {
        int row = i >> 2, seg = i & 3;
        uint32_t so = (uint32_t)row * 80 + seg * 16;
        const __half* off = (const __half*)0 + (size_t)row * 32 + seg * 8;
        CP16(sq + so, qs + (size_t)row * 32 + seg * 8);
        CP16(sk + so, ks + (size_t)row * 32 + seg * 8);
        CP16(sv + so, vs + (size_t)row * 32 + seg * 8);
        (void)off;
    }
    CP_COMMIT(); CP_WAIT0();
    __syncwarp();

    // V transpose in smem: SVt[d][tok] = SVr[tok][d]
    for (int tok = lane; tok < NTOK; tok += 32) {
#pragma unroll
        for (int d = 0; d < 32; d++)
            SVt[d * 72 + tok] = SVr[tok * 40 + d];
    }
    __syncwarp();

    // ---- QK^T (fp16, K=32 -> 2 k16 steps) ----
    float c[4][7][4];
#pragma unroll
    for (int it = 0; it < 4; it++)
#pragma unroll
        for (int jt = 0; jt < 7; jt++)
#pragma unroll
            for (int q = 0; q < 4; q++) c[it][jt][q] = 0.f;

#pragma unroll
    for (int kt = 0; kt < 2; kt++) {
        const int ko = kt * 16;
        uint32_t a[4][4];
#pragma unroll
        for (int it = 0; it < 4; it++) {
            a[it][0] = *reinterpret_cast<const uint32_t*>(&SQ[(it * 16 + g)     * 40 + ko + 2 * t]);
            a[it][1] = *reinterpret_cast<const uint32_t*>(&SQ[(it * 16 + g + 8) * 40 + ko + 2 * t]);
            a[it][2] = *reinterpret_cast<const uint32_t*>(&SQ[(it * 16 + g)     * 40 + ko + 8 + 2 * t]);
            a[it][3] = *reinterpret_cast<const uint32_t*>(&SQ[(it * 16 + g + 8) * 40 + ko + 8 + 2 * t]);
        }
#pragma unroll
        for (int jt = 0; jt < 7; jt++) {
            uint32_t b[2];
            b[0] = *reinterpret_cast<const uint32_t*>(&SK[(jt * 8 + g) * 40 + ko + 2 * t]);
            b[1] = *reinterpret_cast<const uint32_t*>(&SK[(jt * 8 + g) * 40 + ko + 8 + 2 * t]);
#pragma unroll
            for (int it = 0; it < 4; it++) MMA_F16(c[it][jt], a[it], b);
        }
    }

    // ---- masked bias add + softmax (fp32, in accumulators) ----
    const float scale = 0.17677669529663687f;
    int  pi[8];  bool rok[8];
#pragma unroll
    for (int s = 0; s < 8; s++) {
        int tok = (s >> 1) * 16 + g + 8 * (s & 1);
        rok[s] = tok < NTOK;
        int ri = tok / 7, ci = tok - ri * 7;
        pi[s] = ri * 13 + ci + 97;
    }
    int  pj[14]; bool cok[14];
#pragma unroll
    for (int u = 0; u < 14; u++) {
        int jc = (u >> 1) * 8 + 2 * t + (u & 1);
        cok[u] = jc < NTOK;
        int rj = jc / 7, cj = jc - rj * 7;
        pj[u] = rj * 13 + cj;
    }
#pragma unroll
    for (int it = 0; it < 4; it++)
#pragma unroll
        for (int jt = 0; jt < 7; jt++)
#pragma unroll
            for (int q = 0; q < 4; q++) {
                int s = it * 2 + (q >> 1), u = jt * 2 + (q & 1);
                float sc = c[it][jt][q] * scale + Bb[pi[s] - pj[u]];
                c[it][jt][q] = (rok[s] && cok[u]) ? sc : -1e9f;
            }

#pragma unroll
    for (int s = 0; s < 8; s++) {
        const int it = s >> 1, h = s & 1;
        float m = -1e9f;
#pragma unroll
        for (int jt = 0; jt < 7; jt++) {
            m = fmaxf(m, c[it][jt][h * 2]);
            m = fmaxf(m, c[it][jt][h * 2 + 1]);
        }
        m = fmaxf(m, __shfl_xor_sync(0xffffffffu, m, 1));
        m = fmaxf(m, __shfl_xor_sync(0xffffffffu, m, 2));
        float sum = 0.f;
#pragma unroll
        for (int jt = 0; jt < 7; jt++) {
            float p0 = __expf(c[it][jt][h * 2]     - m);
            float p1 = __expf(c[it][jt][h * 2 + 1] - m);
            c[it][jt][h * 2] = p0; c[it][jt][h * 2 + 1] = p1;
            sum += p0 + p1;
        }
        sum += __shfl_xor_sync(0xffffffffu, sum, 1);
        sum += __shfl_xor_sync(0xffffffffu, sum, 2);
        const float inv = 1.0f / sum;
#pragma unroll
        for (int jt = 0; jt < 7; jt++) {
            c[it][jt][h * 2]     *= inv;
            c[it][jt][h * 2 + 1] *= inv;
        }
    }

    // ---- P: accumulators -> fp16 A-fragments in registers ----
    uint32_t pa[4][4][4];
#pragma unroll
    for (int it = 0; it < 4; it++)
#pragma unroll
        for (int kt = 0; kt < 4; kt++) {
            const int jt0 = 2 * kt, jt1 = 2 * kt + 1;
            __half2 h0 = __floats2half2_rn(c[it][jt0][0], c[it][jt0][1]);
            __half2 h1 = __floats2half2_rn(c[it][jt0][2], c[it][jt0][3]);
            pa[it][kt][0] = *reinterpret_cast<uint32_t*>(&h0);
            pa[it][kt][1] = *reinterpret_cast<uint32_t*>(&h1);
            if (jt1 < 7) {
                __half2 h2 = __floats2half2_rn(c[it][jt1][0], c[it][jt1][1]);
                __half2 h3 = __floats2half2_rn(c[it][jt1][2], c[it][jt1][3]);
                pa[it][kt][2] = *reinterpret_cast<uint32_t*>(&h2);
                pa[it][kt][3] = *reinterpret_cast<uint32_t*>(&h3);
            } else {
                pa[it][kt][2] = 0u;
                pa[it][kt][3] = 0u;
            }
        }

    // ---- PV (fp16, K=64 incl. zero pad -> 4 k16 steps) ----
    float d[4][4][4];
#pragma unroll
    for (int it = 0; it < 4; it++)
#pragma unroll
        for (int nt = 0; nt < 4; nt++)
#pragma unroll
            for (int q = 0; q < 4; q++) d[it][nt][q] = 0.f;

#pragma unroll
    for (int kt = 0; kt < 4; kt++) {
        const int ko = kt * 16;
        uint32_t b[4][2];
#pragma unroll
        for (int nt = 0; nt < 4; nt++) {
            b[nt][0] = *reinterpret_cast<const uint32_t*>(&SVt[(nt * 8 + g) * 72 + ko + 2 * t]);
            b[nt][1] = *reinterpret_cast<const uint32_t*>(&SVt[(nt * 8 + g) * 72 + ko + 8 + 2 * t]);
        }
#pragma unroll
        for (int it = 0; it < 4; it++)
#pragma unroll
            for (int nt = 0; nt < 4; nt++) MMA_F16(d[it][nt], pa[it][kt], b[nt]);
    }

    // ---- store half2, k-group-permuted (proj GEMM A operand) ----
    __half* obase = g_attn + (size_t)(win * NTOK) * N_PROJ + head * 32;
#pragma unroll
    for (int it = 0; it < 4; it++)
#pragma unroll
        for (int qq = 0; qq < 2; qq++) {
            int tok = it * 16 + g + 8 * qq;
            if (tok < NTOK) {
                __half* orow = obase + (size_t)tok * N_PROJ;
#pragma unroll
                for (int nt = 0; nt < 4; nt++) {
                    __half2 hv = __floats2half2_rn(d[it][nt][2 * qq], d[it][nt][2 * qq + 1]);
                    int dcol = nt * 8 + 2 * t;          // even -> kperm16 keeps pair adjacent
                    *reinterpret_cast<__half2*>(&orow[kperm16(dcol)]) = hv;
                }
            }
        }
}

// ---------------------------------------------------------------------------
extern "C" void kernel_launch(void* const* d_in, const int* in_sizes, int n_in,
                              void* d_out, int out_size)
{
    const float* x          = (const float*)d_in[0];
    const float* qkv_w      = (const float*)d_in[1];
    const float* qkv_b      = (const float*)d_in[2];
    const float* proj_w     = (const float*)d_in[3];
    const float* proj_b     = (const float*)d_in[4];
    const float* bias_table = (const float*)d_in[5];
    float* out = (float*)d_out;

    __half *qkv_p, *attn_p, *xh_p, *wtq_p, *wtp_p;
    cudaGetSymbolAddress((void**)&qkv_p,  g_qkv);
    cudaGetSymbolAddress((void**)&attn_p, g_attn);
    cudaGetSymbolAddress((void**)&xh_p,   g_xh);
    cudaGetSymbolAddress((void**)&wtq_p,  g_wtq);
    cudaGetSymbolAddress((void**)&wtp_p,  g_wtp);

    cudaFuncSetAttribute((const void*)gemm_h<N_QKV, true, false, true, __half>,
                         cudaFuncAttributeMaxDynamicSharedMemorySize, SMEM_BYTES);
    cudaFuncSetAttribute((const void*)gemm_h<N_PROJ, false, true, false, float>,
                         cudaFuncAttributeMaxDynamicSharedMemorySize, SMEM_BYTES);

    // 0) preprocessing
    {
        int n16 = M_TOTAL * KDIM / 16;
        x_to_half_perm<<<(n16 + 255) / 256, 256>>>((const float4*)x, (uint4*)xh_p, n16);
        transpose_half<<<dim3(N_QKV / 32, KDIM / 32), dim3(32, 8)>>>(qkv_w, wtq_p, KDIM, N_QKV);
        transpose_half<<<dim3(N_PROJ / 32, KDIM / 32), dim3(32, 8)>>>(proj_w, wtp_p, KDIM, N_PROJ);
    }
    // 1) QKV GEMM (fp16 mma, fused gather, head-major slab output)
    gemm_h<N_QKV, true, false, true, __half><<<dim3(N_QKV / BN, M_TOTAL / BM), 256, SMEM_BYTES>>>(
        xh_p, wtq_p, qkv_b, qkv_p);
    // 2) fp16 flash-style window attention (coalesced cp.async staging)
    attn_h_kernel<<<NWIN * HEADS, 32>>>(bias_table);
    // 3) proj GEMM (fp16 mma, fused inverse roll/window scatter)
    gemm_h<N_PROJ, false, true, false, float><<<dim3(N_PROJ / BN, M_TOTAL / BM), 256, SMEM_BYTES>>>(
        attn_p, wtp_p, proj_b, out);
}

// round 12
// speedup vs baseline: 2.3010x; 1.0876x over previous
#include <cuda_runtime.h>
#include <cuda_fp16.h>
#include <cstdint>

// Problem constants (B=32, H=W=56, C=384, heads=12, ws=7, shift=3)
#define HEADS   12
#define WS      7
#define NTOK    49
#define NWIN    2048
#define M_TOTAL (NWIN * NTOK)   // 100352
#define N_QKV   1152
#define N_PROJ  384
#define KDIM    384

// fp16 GEMM tiling: CTA 128x128, 256 threads (8 warps, warp tile 64x32),
// BK=32 halfs (12 K-steps), 4-stage cp.async ring, ldmatrix fragment loads,
// NATURAL k order (ldmatrix does the fragment shuffle; no permutation).
#define BM 128
#define BN 128
#define BK 32
#define KSTEPS (KDIM / BK)        // 12
#define ROW_HALF 40               // halfs per smem row (32 used + 8 pad) = 80B
#define OP_BYTES (BM * ROW_HALF * 2)      // 10240 B per operand per stage
#define STAGE_BYTES (2 * OP_BYTES)        // 20480
#define SMEM_BYTES (4 * STAGE_BYTES)      // 81920

// Scratch. g_qkv holds qkv output in HEAD-MAJOR slabs [tensor*12+head][m][32].
__device__ __half g_qkv[(size_t)M_TOTAL * N_QKV];
__device__ __half g_attn[(size_t)M_TOTAL * N_PROJ];
__device__ __half g_xh [(size_t)M_TOTAL * KDIM];
__device__ __half g_wtq[(size_t)N_QKV * KDIM];
__device__ __half g_wtp[(size_t)N_PROJ * KDIM];

// ---------------------------------------------------------------------------
__device__ __forceinline__ int win_src_index(int m) {
    int win = m / NTOK, t = m - win * NTOK;
    int b  = win >> 6, wi = win & 63;
    int wh = wi >> 3,  ww = wi & 7;
    int r  = t / WS,   c  = t - r * WS;
    int row = wh * WS + r + 3; if (row >= 56) row -= 56;
    int col = ww * WS + c + 3; if (col >= 56) col -= 56;
    return b * 3136 + row * 56 + col;
}

__device__ __forceinline__ uint32_t smem_u32(const void* p) {
    uint32_t a;
    asm("{ .reg .u64 t; cvta.to.shared.u64 t, %1; cvt.u32.u64 %0, t; }" : "=r"(a) : "l"(p));
    return a;
}

#define CP16(dst, src) \
    asm volatile("cp.async.cg.shared.global [%0], [%1], 16;" :: "r"(dst), "l"(src) : "memory")
#define CP_COMMIT() asm volatile("cp.async.commit_group;" ::: "memory")
#define CP_WAIT2()  asm volatile("cp.async.wait_group 2;" ::: "memory")
#define CP_WAIT1()  asm volatile("cp.async.wait_group 1;" ::: "memory")
#define CP_WAIT0()  asm volatile("cp.async.wait_group 0;" ::: "memory")

#define MMA_F16(c, a0, a1, a2, a3, b0, b1) \
    asm volatile("mma.sync.aligned.m16n8k16.row.col.f32.f16.f16.f32 " \
        "{%0,%1,%2,%3}, {%4,%5,%6,%7}, {%8,%9}, {%0,%1,%2,%3};" \
        : "+f"((c)[0]), "+f"((c)[1]), "+f"((c)[2]), "+f"((c)[3]) \
        : "r"(a0), "r"(a1), "r"(a2), "r"(a3), "r"(b0), "r"(b1))

#define LDSM_X4(r0, r1, r2, r3, addr) \
    asm volatile("ldmatrix.sync.aligned.m8n8.x4.shared.b16 {%0,%1,%2,%3}, [%4];" \
        : "=r"(r0), "=r"(r1), "=r"(r2), "=r"(r3) : "r"(addr))

// ---------------------------------------------------------------------------
// fp16 mma.sync GEMM (fp32 accum), ldmatrix fragment loads.
// GATHER: fuse roll/window map into A rows. HEADOUT: [ncol/32][m][32] slab
// output (qkv). SCATTER: fuse inverse roll/window into output rows (proj).
template <int N_TOTAL, bool GATHER, bool SCATTER, bool HEADOUT, typename CT>
__global__ void __launch_bounds__(256, 2)
gemm_h(const __half* __restrict__ A, const __half* __restrict__ WT,
       const float* __restrict__ bias, CT* __restrict__ C)
{
    extern __shared__ __half smh[];
    const uint32_t smb = smem_u32(smh);

    const int tid  = threadIdx.x;
    const int wid  = tid >> 5, lane = tid & 31;
    const int t    = lane & 3;
    const int wm   = wid & 1, wn = wid >> 1;     // warp grid 2(M) x 4(N)
    const int m0   = blockIdx.y * BM, n0 = blockIdx.x * BN;

    // gmem->smem: 2 threads per row, 16 halfs (32B = 2x CP16) each
    const int lrow = tid >> 1, lseg = (tid & 1) * 16;
    const __half* arow = A + (size_t)(GATHER ? win_src_index(m0 + lrow) : (m0 + lrow)) * KDIM + lseg;
    const __half* brow = WT + (size_t)(n0 + lrow) * KDIM + lseg;
    const uint32_t a_dst = smb + (uint32_t)lrow * (ROW_HALF * 2) + lseg * 2;
    const uint32_t b_dst = a_dst + OP_BYTES;

    auto load_stage = [&](int s, int kt) {
        const uint32_t so = (uint32_t)s * STAGE_BYTES;
        const __half* ap = arow + kt * BK;
        const __half* bp = brow + kt * BK;
        CP16(a_dst + so,      ap);
        CP16(a_dst + so + 16, ap + 8);
        CP16(b_dst + so,      bp);
        CP16(b_dst + so + 16, bp + 8);
    };

    // ldmatrix lane addressing (x4 = four 8x8 b16 tiles)
    const int l7  = lane & 7;
    const int l8  = (lane >> 3) & 1;
    const int l16 = (lane >> 4) & 1;
    // A tiles per (it): t0=rows 0-7 k0-7, t1=rows 8-15 k0-7, t2=rows 0-7 k8-15, t3=rows 8-15 k8-15
    uint32_t a_addr[4];
#pragma unroll
    for (int it = 0; it < 4; it++)
        a_addr[it] = smb + (uint32_t)(((wm * 64 + it * 16 + l7 + l8 * 8) * ROW_HALF + l16 * 8) * 2);
    // B tiles per (jp): t0=jt(2jp) k0-7, t1=jt(2jp) k8-15, t2=jt(2jp+1) k0-7, t3=jt(2jp+1) k8-15
    uint32_t b_addr[2];
#pragma unroll
    for (int jp = 0; jp < 2; jp++)
        b_addr[jp] = smb + OP_BYTES
                   + (uint32_t)(((wn * 32 + jp * 16 + l16 * 8 + l7) * ROW_HALF + l8 * 8) * 2);

    float c[4][4][4];
#pragma unroll
    for (int i = 0; i < 4; i++)
#pragma unroll
        for (int j = 0; j < 4; j++)
#pragma unroll
            for (int q = 0; q < 4; q++) c[i][j][q] = 0.f;

#pragma unroll
    for (int s = 0; s < 3; s++) { load_stage(s, s); CP_COMMIT(); }

#pragma unroll 4
    for (int kt = 0; kt < KSTEPS; kt++) {
        const int rem = KSTEPS - 1 - kt;
        if (rem >= 2)      CP_WAIT2();
        else if (rem == 1) CP_WAIT1();
        else               CP_WAIT0();
        __syncthreads();

        if (kt + 3 < KSTEPS) { load_stage((kt + 3) & 3, kt + 3); CP_COMMIT(); }

        const uint32_t soff = (uint32_t)(kt & 3) * STAGE_BYTES;

#pragma unroll
        for (int ks = 0; ks < 2; ks++) {          // two k16 sub-steps per BK=32
            const uint32_t ko = soff + ks * 32;   // 16 halfs = 32 bytes
            uint32_t a[4][4];
#pragma unroll
            for (int it = 0; it < 4; it++)
                LDSM_X4(a[it][0], a[it][1], a[it][2], a[it][3], a_addr[it] + ko);
            uint32_t b[2][4];
#pragma unroll
            for (int jp = 0; jp < 2; jp++)
                LDSM_X4(b[jp][0], b[jp][1], b[jp][2], b[jp][3], b_addr[jp] + ko);
#pragma unroll
            for (int it = 0; it < 4; it++)
#pragma unroll
                for (int jt = 0; jt < 4; jt++)
                    MMA_F16(c[it][jt], a[it][0], a[it][1], a[it][2], a[it][3],
                            b[jt >> 1][2 * (jt & 1)], b[jt >> 1][2 * (jt & 1) + 1]);
        }
    }

    // epilogue: fp32 bias add; each 4-lane group stores 32B contiguous
    const int g = lane >> 2;
    const int ncolb = n0 + wn * 32;
    float2 bj[4];
#pragma unroll
    for (int j = 0; j < 4; j++)
        bj[j] = *reinterpret_cast<const float2*>(&bias[ncolb + j * 8 + 2 * t]);

#pragma unroll
    for (int i = 0; i < 4; i++) {
        const int mrow = m0 + wm * 64 + i * 16 + g;
        CT *p0, *p1;
        if (HEADOUT) {
            const size_t slab = (size_t)(ncolb >> 5) * M_TOTAL;
            p0 = C + (slab + mrow)     * 32 + 2 * t;
            p1 = C + (slab + mrow + 8) * 32 + 2 * t;
        } else {
            const size_t r0 = SCATTER ? (size_t)win_src_index(mrow)     : (size_t)mrow;
            const size_t r1 = SCATTER ? (size_t)win_src_index(mrow + 8) : (size_t)(mrow + 8);
            p0 = C + r0 * N_TOTAL + ncolb + 2 * t;
            p1 = C + r1 * N_TOTAL + ncolb + 2 * t;
        }
#pragma unroll
        for (int j = 0; j < 4; j++) {
            float x0 = c[i][j][0] + bj[j].x, y0 = c[i][j][1] + bj[j].y;
            float x1 = c[i][j][2] + bj[j].x, y1 = c[i][j][3] + bj[j].y;
            if (sizeof(CT) == 2) {
                *reinterpret_cast<__half2*>(p0 + j * 8) = __floats2half2_rn(x0, y0);
                *reinterpret_cast<__half2*>(p1 + j * 8) = __floats2half2_rn(x1, y1);
            } else {
                *reinterpret_cast<float2*>(p0 + j * 8) = make_float2(x0, y0);
                *reinterpret_cast<float2*>(p1 + j * 8) = make_float2(x1, y1);
            }
        }
    }
}

// ---------------------------------------------------------------------------
// Preprocessing (natural k order — ldmatrix needs no permutation)
__global__ void transpose_half(const float* __restrict__ W, __half* __restrict__ WT,
                               int K, int N)
{
    __shared__ float tbuf[32][33];
    const int n0 = blockIdx.x * 32, k0 = blockIdx.y * 32;
    const int tx = threadIdx.x, ty = threadIdx.y;
#pragma unroll
    for (int i = 0; i < 4; i++)
        tbuf[ty + 8 * i][tx] = W[(size_t)(k0 + ty + 8 * i) * N + n0 + tx];
    __syncthreads();
#pragma unroll
    for (int i = 0; i < 4; i++)
        WT[(size_t)(n0 + ty + 8 * i) * K + k0 + tx] = __float2half_rn(tbuf[tx][ty + 8 * i]);
}

__global__ void x_to_half(const float4* __restrict__ in, uint4* __restrict__ out, int n8)
{
    int i = blockIdx.x * blockDim.x + threadIdx.x;
    if (i < n8) {
        float4 v0 = in[2 * i], v1 = in[2 * i + 1];
        __half2 o[4];
        o[0] = __floats2half2_rn(v0.x, v0.y);
        o[1] = __floats2half2_rn(v0.z, v0.w);
        o[2] = __floats2half2_rn(v1.x, v1.y);
        o[3] = __floats2half2_rn(v1.z, v1.w);
        out[i] = *reinterpret_cast<uint4*>(o);
    }
}

// ---------------------------------------------------------------------------
// fp16 flash-style window attention: one warp per (win,head), coalesced
// cp.async staging from head-major slabs, in-register P handoff.
__global__ void __launch_bounds__(32)
attn_h_kernel(const float* __restrict__ bias_table)
{
    const int head = blockIdx.x % HEADS;
    const int win  = blockIdx.x / HEADS;
    const int lane = threadIdx.x;
    const int g = lane >> 2, t = lane & 3;

    __shared__ __half SQ[64 * 40];   // [token][dim], stride 40 halfs
    __shared__ __half SK[56 * 40];
    __shared__ __half SVr[49 * 40];  // V rows staging
    __shared__ __half SVt[32 * 72];  // [dim][token], stride 72 halfs
    __shared__ float  Bb[224];       // bias, +-13 guard pad: index 13+rel

    for (int i = lane; i < 224; i += 32) Bb[i] = 0.f;
    __syncwarp();
    for (int i = lane; i < 169; i += 32) Bb[13 + i] = __ldg(&bias_table[i * HEADS + head]);

    {
        const uint4 z = make_uint4(0, 0, 0, 0);
        uint4* v4 = reinterpret_cast<uint4*>(SVt);
        for (int i = lane; i < 32 * 72 * 2 / 16; i += 32) v4[i] = z;
    }

    const size_t mb = (size_t)win * NTOK;
    const __half* qs = g_qkv + ((size_t)(0 * HEADS + head) * M_TOTAL + mb) * 32;
    const __half* ks = g_qkv + ((size_t)(1 * HEADS + head) * M_TOTAL + mb) * 32;
    const __half* vs = g_qkv + ((size_t)(2 * HEADS + head) * M_TOTAL + mb) * 32;
    const uint32_t sq = smem_u32(SQ), sk = smem_u32(SK), sv = smem_u32(SVr);
    for (int i = lane; i < NTOK * 4; i += 32) {
        int row = i >> 2, seg = i & 3;
        uint32_t so = (uint32_t)row * 80 + seg * 16;
        CP16(sq + so, qs + (size_t)row * 32 + seg * 8);
        CP16(sk + so, ks + (size_t)row * 32 + seg * 8);
        CP16(sv + so, vs + (size_t)row * 32 + seg * 8);
    }
    CP_COMMIT(); CP_WAIT0();
    __syncwarp();

    for (int tok = lane; tok < NTOK; tok += 32) {
#pragma unroll
        for (int d = 0; d < 32; d++)
            SVt[d * 72 + tok] = SVr[tok * 40 + d];
    }
    __syncwarp();

    // ---- QK^T ----
    float c[4][7][4];
#pragma unroll
    for (int it = 0; it < 4; it++)
#pragma unroll
        for (int jt = 0; jt < 7; jt++)
#pragma unroll
            for (int q = 0; q < 4; q++) c[it][jt][q] = 0.f;

#pragma unroll
    for (int kt = 0; kt < 2; kt++) {
        const int ko = kt * 16;
        uint32_t a[4][4];
#pragma unroll
        for (int it = 0; it < 4; it++) {
            a[it][0] = *reinterpret_cast<const uint32_t*>(&SQ[(it * 16 + g)     * 40 + ko + 2 * t]);
            a[it][1] = *reinterpret_cast<const uint32_t*>(&SQ[(it * 16 + g + 8) * 40 + ko + 2 * t]);
            a[it][2] = *reinterpret_cast<const uint32_t*>(&SQ[(it * 16 + g)     * 40 + ko + 8 + 2 * t]);
            a[it][3] = *reinterpret_cast<const uint32_t*>(&SQ[(it * 16 + g + 8) * 40 + ko + 8 + 2 * t]);
        }
#pragma unroll
        for (int jt = 0; jt < 7; jt++) {
            uint32_t b0 = *reinterpret_cast<const uint32_t*>(&SK[(jt * 8 + g) * 40 + ko + 2 * t]);
            uint32_t b1 = *reinterpret_cast<const uint32_t*>(&SK[(jt * 8 + g) * 40 + ko + 8 + 2 * t]);
#pragma unroll
            for (int it = 0; it < 4; it++)
                MMA_F16(c[it][jt], a[it][0], a[it][1], a[it][2], a[it][3], b0, b1);
        }
    }

    // ---- masked bias add + softmax ----
    const float scale = 0.17677669529663687f;
    int  pi[8];  bool rok[8];
#pragma unroll
    for (int s = 0; s < 8; s++) {
        int tok = (s >> 1) * 16 + g + 8 * (s & 1);
        rok[s] = tok < NTOK;
        int ri = tok / 7, ci = tok - ri * 7;
        pi[s] = ri * 13 + ci + 97;
    }
    int  pj[14]; bool cok[14];
#pragma unroll
    for (int u = 0; u < 14; u++) {
        int jc = (u >> 1) * 8 + 2 * t + (u & 1);
        cok[u] = jc < NTOK;
        int rj = jc / 7, cj = jc - rj * 7;
        pj[u] = rj * 13 + cj;
    }
#pragma unroll
    for (int it = 0; it < 4; it++)
#pragma unroll
        for (int jt = 0; jt < 7; jt++)
#pragma unroll
            for (int q = 0; q < 4; q++) {
                int s = it * 2 + (q >> 1), u = jt * 2 + (q & 1);
                float sc = c[it][jt][q] * scale + Bb[pi[s] - pj[u]];
                c[it][jt][q] = (rok[s] && cok[u]) ? sc : -1e9f;
            }

#pragma unroll
    for (int s = 0; s < 8; s++) {
        const int it = s >> 1, h = s & 1;
        float m = -1e9f;
#pragma unroll
        for (int jt = 0; jt < 7; jt++) {
            m = fmaxf(m, c[it][jt][h * 2]);
            m = fmaxf(m, c[it][jt][h * 2 + 1]);
        }
        m = fmaxf(m, __shfl_xor_sync(0xffffffffu, m, 1));
        m = fmaxf(m, __shfl_xor_sync(0xffffffffu, m, 2));
        float sum = 0.f;
#pragma unroll
        for (int jt = 0; jt < 7; jt++) {
            float p0 = __expf(c[it][jt][h * 2]     - m);
            float p1 = __expf(c[it][jt][h * 2 + 1] - m);
            c[it][jt][h * 2] = p0; c[it][jt][h * 2 + 1] = p1;
            sum += p0 + p1;
        }
        sum += __shfl_xor_sync(0xffffffffu, sum, 1);
        sum += __shfl_xor_sync(0xffffffffu, sum, 2);
        const float inv = 1.0f / sum;
#pragma unroll
        for (int jt = 0; jt < 7; jt++) {
            c[it][jt][h * 2]     *= inv;
            c[it][jt][h * 2 + 1] *= inv;
        }
    }

    // ---- P: accumulators -> fp16 A-fragments in registers ----
    uint32_t pa[4][4][4];
#pragma unroll
    for (int it = 0; it < 4; it++)
#pragma unroll
        for (int kt = 0; kt < 4; kt++) {
            const int jt0 = 2 * kt, jt1 = 2 * kt + 1;
            __half2 h0 = __floats2half2_rn(c[it][jt0][0], c[it][jt0][1]);
            __half2 h1 = __floats2half2_rn(c[it][jt0][2], c[it][jt0][3]);
            pa[it][kt][0] = *reinterpret_cast<uint32_t*>(&h0);
            pa[it][kt][1] = *reinterpret_cast<uint32_t*>(&h1);
            if (jt1 < 7) {
                __half2 h2 = __floats2half2_rn(c[it][jt1][0], c[it][jt1][1]);
                __half2 h3 = __floats2half2_rn(c[it][jt1][2], c[it][jt1][3]);
                pa[it][kt][2] = *reinterpret_cast<uint32_t*>(&h2);
                pa[it][kt][3] = *reinterpret_cast<uint32_t*>(&h3);
            } else {
                pa[it][kt][2] = 0u;
                pa[it][kt][3] = 0u;
            }
        }

    // ---- PV ----
    float d[4][4][4];
#pragma unroll
    for (int it = 0; it < 4; it++)
#pragma unroll
        for (int nt = 0; nt < 4; nt++)
#pragma unroll
            for (int q = 0; q < 4; q++) d[it][nt][q] = 0.f;

#pragma unroll
    for (int kt = 0; kt < 4; kt++) {
        const int ko = kt * 16;
        uint32_t b[4][2];
#pragma unroll
        for (int nt = 0; nt < 4; nt++) {
            b[nt][0] = *reinterpret_cast<const uint32_t*>(&SVt[(nt * 8 + g) * 72 + ko + 2 * t]);
            b[nt][1] = *reinterpret_cast<const uint32_t*>(&SVt[(nt * 8 + g) * 72 + ko + 8 + 2 * t]);
        }
#pragma unroll
        for (int it = 0; it < 4; it++)
#pragma unroll
            for (int nt = 0; nt < 4; nt++)
                MMA_F16(d[it][nt], pa[it][kt][0], pa[it][kt][1], pa[it][kt][2], pa[it][kt][3],
                        b[nt][0], b[nt][1]);
    }

    // ---- store half2, natural order (proj GEMM reads natural now) ----
    __half* obase = g_attn + (size_t)(win * NTOK) * N_PROJ + head * 32;
#pragma unroll
    for (int it = 0; it < 4; it++)
#pragma unroll
        for (int qq = 0; qq < 2; qq++) {
            int tok = it * 16 + g + 8 * qq;
            if (tok < NTOK) {
                __half* orow = obase + (size_t)tok * N_PROJ;
#pragma unroll
                for (int nt = 0; nt < 4; nt++) {
                    __half2 hv = __floats2half2_rn(d[it][nt][2 * qq], d[it][nt][2 * qq + 1]);
                    *reinterpret_cast<__half2*>(&orow[nt * 8 + 2 * t]) = hv;
                }
            }
        }
}

// ---------------------------------------------------------------------------
extern "C" void kernel_launch(void* const* d_in, const int* in_sizes, int n_in,
                              void* d_out, int out_size)
{
    const float* x          = (const float*)d_in[0];
    const float* qkv_w      = (const float*)d_in[1];
    const float* qkv_b      = (const float*)d_in[2];
    const float* proj_w     = (const float*)d_in[3];
    const float* proj_b     = (const float*)d_in[4];
    const float* bias_table = (const float*)d_in[5];
    float* out = (float*)d_out;

    __half *qkv_p, *attn_p, *xh_p, *wtq_p, *wtp_p;
    cudaGetSymbolAddress((void**)&qkv_p,  g_qkv);
    cudaGetSymbolAddress((void**)&attn_p, g_attn);
    cudaGetSymbolAddress((void**)&xh_p,   g_xh);
    cudaGetSymbolAddress((void**)&wtq_p,  g_wtq);
    cudaGetSymbolAddress((void**)&wtp_p,  g_wtp);

    cudaFuncSetAttribute((const void*)gemm_h<N_QKV, true, false, true, __half>,
                         cudaFuncAttributeMaxDynamicSharedMemorySize, SMEM_BYTES);
    cudaFuncSetAttribute((const void*)gemm_h<N_PROJ, false, true, false, float>,
                         cudaFuncAttributeMaxDynamicSharedMemorySize, SMEM_BYTES);

    // 0) preprocessing (fp16 rn; natural order; weights -> K-major)
    {
        int n8 = M_TOTAL * KDIM / 8;
        x_to_half<<<(n8 + 255) / 256, 256>>>((const float4*)x, (uint4*)xh_p, n8);
        transpose_half<<<dim3(N_QKV / 32, KDIM / 32), dim3(32, 8)>>>(qkv_w, wtq_p, KDIM, N_QKV);
        transpose_half<<<dim3(N_PROJ / 32, KDIM / 32), dim3(32, 8)>>>(proj_w, wtp_p, KDIM, N_PROJ);
    }
    // 1) QKV GEMM (fp16 mma + ldmatrix, fused gather, head-major slab output)
    gemm_h<N_QKV, true, false, true, __half><<<dim3(N_QKV / BN, M_TOTAL / BM), 256, SMEM_BYTES>>>(
        xh_p, wtq_p, qkv_b, qkv_p);
    // 2) fp16 flash-style window attention
    attn_h_kernel<<<NWIN * HEADS, 32>>>(bias_table);
    // 3) proj GEMM (fp16 mma + ldmatrix, fused inverse roll/window scatter)
    gemm_h<N_PROJ, false, true, false, float><<<dim3(N_PROJ / BN, M_TOTAL / BM), 256, SMEM_BYTES>>>(
        attn_p, wtp_p, proj_b, out);
}